// round 2
// baseline (speedup 1.0000x reference)
#include <cuda_runtime.h>
#include <math.h>

#define B_  32
#define T_  64
#define E_  512
#define H_  512
#define V_  10000
#define G_  2048   // 4*H

// ------------------------- device scratch (no allocs allowed) ---------------
__device__ float g_X   [T_ * B_ * E_];   // 4 MB   xs, row m = t*32+b
__device__ float g_Gin [T_ * B_ * G_];   // 16 MB  precomputed x@W_ih^T + b_ih + b_hh
__device__ float g_hs  [T_ * B_ * H_];   // 4 MB   LSTM outputs, row m = t*32+b
__device__ float g_hT  [H_ * B_];        // 64 KB  h transposed [k][b]
__device__ float g_biasg[G_];
__device__ unsigned g_barcnt;
__device__ unsigned g_bargen;

// ------------------------- prep: build X and fused bias ---------------------
// captions: JAX silently downcasts int64->int32 (x64 disabled), so read int32.
// Token index clamped defensively so a dtype surprise shows up as rel_err,
// not an illegal access.
__global__ void prep_kernel(const float* __restrict__ features,
                            const int* __restrict__ captions,
                            const float* __restrict__ embed,
                            const float* __restrict__ b_ih,
                            const float* __restrict__ b_hh)
{
    int idx = blockIdx.x * blockDim.x + threadIdx.x;   // over T*B*E = 1,048,576
    int e = idx & (E_ - 1);
    int b = (idx >> 9) & (B_ - 1);
    int t = idx >> 14;
    float v;
    if (t == 0) {
        v = features[b * E_ + e];
    } else {
        int tok = captions[b * T_ + (t - 1)];
        tok = min(max(tok, 0), V_ - 1);
        v = embed[(size_t)tok * E_ + e];
    }
    g_X[idx] = v;
    if (idx < G_) g_biasg[idx] = b_ih[idx] + b_hh[idx];
}

// ------------------------- generic SGEMM: C = A(MxK) * B(NxK)^T + bias ------
// EPI 0: C[m*N+n] = acc + bias[n]            (Gin)
// EPI 1: out[b][t][n] = acc + bias[n], m=t*32+b  (FC -> final output)
template<int EPI>
__global__ void __launch_bounds__(256)
sgemm_kernel(const float* __restrict__ A, const float* __restrict__ Bm,
             const float* __restrict__ bias, float* __restrict__ C,
             int M, int N, int K)
{
    const int BM = 128, BN = 128, BK = 32;
    __shared__ float As[BK][BM + 4];
    __shared__ float Bs[BK][BN + 4];

    int tid = threadIdx.x;
    int m0 = blockIdx.y * BM;
    int n0 = blockIdx.x * BN;
    int ty = tid >> 4, tx = tid & 15;

    float acc[8][8];
#pragma unroll
    for (int i = 0; i < 8; i++)
#pragma unroll
        for (int j = 0; j < 8; j++) acc[i][j] = 0.f;

    for (int k0 = 0; k0 < K; k0 += BK) {
#pragma unroll
        for (int r = 0; r < 4; ++r) {
            int s = tid + r * 256;
            int row = s >> 3, kq = s & 7;
            float4 v = *(const float4*)&A[(size_t)(m0 + row) * K + k0 + kq * 4];
            As[kq * 4 + 0][row] = v.x; As[kq * 4 + 1][row] = v.y;
            As[kq * 4 + 2][row] = v.z; As[kq * 4 + 3][row] = v.w;
        }
#pragma unroll
        for (int r = 0; r < 4; ++r) {
            int s = tid + r * 256;
            int row = s >> 3, kq = s & 7;
            float4 v = make_float4(0.f, 0.f, 0.f, 0.f);
            if (n0 + row < N)
                v = *(const float4*)&Bm[(size_t)(n0 + row) * K + k0 + kq * 4];
            Bs[kq * 4 + 0][row] = v.x; Bs[kq * 4 + 1][row] = v.y;
            Bs[kq * 4 + 2][row] = v.z; Bs[kq * 4 + 3][row] = v.w;
        }
        __syncthreads();
#pragma unroll
        for (int kk = 0; kk < BK; ++kk) {
            float4 a0 = *(const float4*)&As[kk][ty * 8];
            float4 a1 = *(const float4*)&As[kk][ty * 8 + 4];
            float4 b0 = *(const float4*)&Bs[kk][tx * 8];
            float4 b1 = *(const float4*)&Bs[kk][tx * 8 + 4];
            float av[8] = {a0.x, a0.y, a0.z, a0.w, a1.x, a1.y, a1.z, a1.w};
            float bv[8] = {b0.x, b0.y, b0.z, b0.w, b1.x, b1.y, b1.z, b1.w};
#pragma unroll
            for (int i = 0; i < 8; i++)
#pragma unroll
                for (int j = 0; j < 8; j++)
                    acc[i][j] += av[i] * bv[j];
        }
        __syncthreads();
    }

#pragma unroll
    for (int i = 0; i < 8; i++) {
        int m = m0 + ty * 8 + i;
        float* crow;
        if (EPI == 0) {
            crow = C + (size_t)m * N;
        } else {
            int t = m >> 5, b = m & 31;
            crow = C + (size_t)b * (T_ * V_) + (size_t)t * V_;
        }
#pragma unroll
        for (int j = 0; j < 8; j++) {
            int n = n0 + tx * 8 + j;
            if (n < N) crow[n] = acc[i][j] + bias[n];
        }
    }
}

// ------------------------- persistent LSTM recurrence -----------------------
// 128 CTAs x 256 threads. CTA bx owns hidden slice jh in [bx*4, bx*4+4),
// i.e. 16 gate rows j = g*512 + jh (g = gate index i/f/g/o).
// W_hh slice (16x512 fp32 = 32KB) cached in smem for all 64 steps.
// Warp w owns k-chunk [64w, 64w+64); lane = batch b; h chunk in registers.
#define LSTM_NCTA 128

__device__ __forceinline__ float sigmoidf_(float x) { return 1.f / (1.f + expf(-x)); }

__global__ void __launch_bounds__(256, 1)
lstm_kernel(const float* __restrict__ Whh)
{
    __shared__ float Ws[16 * 512];        // 32 KB
    __shared__ float red[4 * 16 * 32];    // 8 KB  (two-phase reduction)

    const int tid  = threadIdx.x;
    const int bx   = blockIdx.x;
    const int w    = tid >> 5;
    const int lane = tid & 31;

    // load W_hh slice into smem (once; reused for all 64 steps)
    for (int s = tid; s < 16 * 512; s += 256) {
        int jl = s >> 9, k = s & 511;
        int g  = jl >> 2;
        int jh = (bx << 2) + (jl & 3);
        Ws[s] = Whh[(size_t)(g * 512 + jh) * 512 + k];
    }

    // update-thread state (tid < 128): jh_l = tid>>5 in [0,4), b = lane
    float c_state = 0.f;
    const int jh_l    = tid >> 5;
    const int jh_glob = (bx << 2) + jh_l;
    __syncthreads();

    float hreg[64];
    float accv[16];

    for (int t = 0; t < 64; ++t) {
        if (t > 0) {
            // load my h chunk (transposed layout -> coalesced), L2-fresh
#pragma unroll
            for (int i = 0; i < 64; ++i)
                hreg[i] = __ldcg(&g_hT[(w * 64 + i) * 32 + lane]);
            // partial gates for my k-chunk, all 16 gate rows
#pragma unroll
            for (int jl = 0; jl < 16; ++jl) {
                const float4* wv = (const float4*)&Ws[jl * 512 + w * 64];
                float a = 0.f;
#pragma unroll
                for (int q = 0; q < 16; ++q) {
                    float4 v = wv[q];
                    a += v.x * hreg[q * 4 + 0] + v.y * hreg[q * 4 + 1]
                       + v.z * hreg[q * 4 + 2] + v.w * hreg[q * 4 + 3];
                }
                accv[jl] = a;
            }
            if (w < 4) {
#pragma unroll
                for (int jl = 0; jl < 16; ++jl)
                    red[(w * 16 + jl) * 32 + lane] = accv[jl];
            }
        }
        __syncthreads();
        if (t > 0 && w >= 4) {
#pragma unroll
            for (int jl = 0; jl < 16; ++jl)
                red[((w - 4) * 16 + jl) * 32 + lane] += accv[jl];
        }
        __syncthreads();

        if (tid < 128) {
            const int b = lane;
            float gv[4];
#pragma unroll
            for (int g = 0; g < 4; ++g) {
                float s = 0.f;
                if (t > 0) {
                    int jl = g * 4 + jh_l;
#pragma unroll
                    for (int ww = 0; ww < 4; ++ww)
                        s += red[(ww * 16 + jl) * 32 + b];
                }
                gv[g] = g_Gin[(size_t)(t * 32 + b) * G_ + g * 512 + jh_glob] + s;
            }
            float i_ = sigmoidf_(gv[0]);
            float f_ = sigmoidf_(gv[1]);
            float gg = tanhf(gv[2]);
            float o_ = sigmoidf_(gv[3]);
            c_state = f_ * c_state + i_ * gg;
            float h = o_ * tanhf(c_state);
            g_hT[jh_glob * 32 + b] = h;
            g_hs[(size_t)(t * 32 + b) * H_ + jh_glob] = h;
        }

        // ---- grid barrier (all CTAs co-resident: 128 <= 148 SMs) ----
        __threadfence();
        __syncthreads();
        if (tid == 0) {
            unsigned gen = *(volatile unsigned*)&g_bargen;
            unsigned arrived = atomicAdd(&g_barcnt, 1u);
            if (arrived == LSTM_NCTA - 1) {
                g_barcnt = 0;
                __threadfence();
                atomicAdd(&g_bargen, 1u);
            } else {
                while (*(volatile unsigned*)&g_bargen == gen) { }
            }
        }
        __syncthreads();
    }
}

// ------------------------- launch ------------------------------------------
extern "C" void kernel_launch(void* const* d_in, const int* in_sizes, int n_in,
                              void* d_out, int out_size)
{
    const float* features = (const float*)d_in[0];
    const int*   captions = (const int*)d_in[1];
    // d_in[2] = forward_approach (unused)
    const float* embed = (const float*)d_in[3];
    const float* W_ih  = (const float*)d_in[4];
    const float* W_hh  = (const float*)d_in[5];
    const float* b_ih  = (const float*)d_in[6];
    const float* b_hh  = (const float*)d_in[7];
    const float* fc_W  = (const float*)d_in[8];
    const float* fc_b  = (const float*)d_in[9];
    float* out = (float*)d_out;

    float *pX, *pGin, *phs, *pbias;
    cudaGetSymbolAddress((void**)&pX,    g_X);
    cudaGetSymbolAddress((void**)&pGin,  g_Gin);
    cudaGetSymbolAddress((void**)&phs,   g_hs);
    cudaGetSymbolAddress((void**)&pbias, g_biasg);

    // 1) build X + fused bias
    prep_kernel<<<(T_ * B_ * E_) / 256, 256>>>(features, captions, embed, b_ih, b_hh);

    // 2) Gin = X @ W_ih^T + (b_ih + b_hh)    (2048 x 2048, K=512)
    sgemm_kernel<0><<<dim3(G_ / 128, (T_ * B_) / 128), 256>>>(
        pX, W_ih, pbias, pGin, T_ * B_, G_, E_);

    // 3) persistent LSTM recurrence (64 steps)
    lstm_kernel<<<LSTM_NCTA, 256>>>(W_hh);

    // 4) logits = hs @ fc_W^T + fc_b, written directly as (B, T, V)
    sgemm_kernel<1><<<dim3((V_ + 127) / 128, (T_ * B_) / 128), 256>>>(
        phs, fc_W, fc_b, out, T_ * B_, V_, H_);
}

// round 4
// speedup vs baseline: 1.6574x; 1.6574x over previous
#include <cuda_runtime.h>
#include <cuda_bf16.h>
#include <math.h>
#include <stdint.h>

#define B_  32
#define T_  64
#define E_  512
#define H_  512
#define V_  10000
#define G_  2048          // 4*H
#define VPAD 10112        // 79 * 128

// ------------------------- device scratch (no allocs allowed) ---------------
__device__ __nv_bfloat16 g_Xh  [T_ * B_ * E_];
__device__ __nv_bfloat16 g_Xl  [T_ * B_ * E_];
__device__ __nv_bfloat16 g_Wih_h[G_ * E_];
__device__ __nv_bfloat16 g_Wih_l[G_ * E_];
__device__ __nv_bfloat16 g_fcW_h[VPAD * H_];
__device__ __nv_bfloat16 g_fcW_l[VPAD * H_];
__device__ __nv_bfloat16 g_hs_h[T_ * B_ * H_];
__device__ __nv_bfloat16 g_hs_l[T_ * B_ * H_];
__device__ float g_Gin [T_ * B_ * G_];
__device__ float g_hT  [H_ * B_];
__device__ float g_biasg[G_];
__device__ unsigned g_barcnt;
__device__ unsigned g_bargen;

// ------------------------- mma.sync helpers (sm_80+ baseline PTX) -----------
__device__ __forceinline__ uint32_t smem_u32(const void* p) {
    uint32_t a;
    asm("{ .reg .u64 t; cvta.to.shared.u64 t, %1; cvt.u32.u64 %0, t; }"
        : "=r"(a) : "l"(p));
    return a;
}
__device__ __forceinline__ void ldsm4(uint32_t& r0, uint32_t& r1,
                                      uint32_t& r2, uint32_t& r3, uint32_t addr) {
    asm volatile("ldmatrix.sync.aligned.m8n8.x4.shared.b16 {%0,%1,%2,%3}, [%4];"
                 : "=r"(r0), "=r"(r1), "=r"(r2), "=r"(r3) : "r"(addr));
}
__device__ __forceinline__ void mma_bf16(float* d, const uint32_t* a, const uint32_t* b) {
    asm volatile(
        "mma.sync.aligned.m16n8k16.row.col.f32.bf16.bf16.f32 "
        "{%0,%1,%2,%3}, {%4,%5,%6,%7}, {%8,%9}, {%0,%1,%2,%3};"
        : "+f"(d[0]), "+f"(d[1]), "+f"(d[2]), "+f"(d[3])
        : "r"(a[0]), "r"(a[1]), "r"(a[2]), "r"(a[3]), "r"(b[0]), "r"(b[1]));
}

// ------------------------- prep: split-X + fused bias -----------------------
__global__ void prep_kernel(const float* __restrict__ features,
                            const int* __restrict__ captions,
                            const float* __restrict__ embed,
                            const float* __restrict__ b_ih,
                            const float* __restrict__ b_hh)
{
    int idx = blockIdx.x * blockDim.x + threadIdx.x;   // T*B*E = 1,048,576
    int e = idx & (E_ - 1);
    int b = (idx >> 9) & (B_ - 1);
    int t = idx >> 14;
    float v;
    if (t == 0) {
        v = features[b * E_ + e];
    } else {
        int tok = captions[b * T_ + (t - 1)];
        tok = min(max(tok, 0), V_ - 1);
        v = embed[(size_t)tok * E_ + e];
    }
    __nv_bfloat16 h = __float2bfloat16(v);
    g_Xh[idx] = h;
    g_Xl[idx] = __float2bfloat16(v - __bfloat162float(h));
    if (idx < G_) g_biasg[idx] = b_ih[idx] + b_hh[idx];
}

// ------------------------- weight split -------------------------------------
__global__ void split_kernel(const float* __restrict__ src,
                             __nv_bfloat16* __restrict__ hi,
                             __nv_bfloat16* __restrict__ lo,
                             int n_valid, int n_pad)
{
    int i = blockIdx.x * 256 + threadIdx.x;
    if (i >= n_pad) return;
    float v = (i < n_valid) ? src[i] : 0.f;
    __nv_bfloat16 h = __float2bfloat16(v);
    hi[i] = h;
    lo[i] = __float2bfloat16(v - __bfloat162float(h));
}

// ------------------------- mma.sync GEMM: C = A * B^T + bias ----------------
// A[M x 512] split (Ah,Al), B[Npad x 512] split (Bh,Bl), bf16 K-major.
// 3-pass: Ah*Bh + Ah*Bl + Al*Bh, fp32 accum in registers.
// CTA tile 128x128, 8 warps of 32x64, K-chunk 32 (16 chunks).
// EPI 0: C[m*Nlog + n]                     (Gin)
// EPI 1: C[(m&31)*T*V + (m>>5)*V + n]      (FC output remap)
#define TS 40   // smem row stride in bf16 (32 + 8 pad): conflict-free

template<int EPI>
__global__ void __launch_bounds__(256, 2)
mma_gemm(const __nv_bfloat16* __restrict__ Ah, const __nv_bfloat16* __restrict__ Al,
         const __nv_bfloat16* __restrict__ Bh, const __nv_bfloat16* __restrict__ Bl,
         const float* __restrict__ bias, float* __restrict__ C, int Nlog)
{
    __shared__ __nv_bfloat16 sAh[128 * TS];
    __shared__ __nv_bfloat16 sAl[128 * TS];
    __shared__ __nv_bfloat16 sBh[128 * TS];
    __shared__ __nv_bfloat16 sBl[128 * TS];
    __shared__ float bias_s[128];

    const int tid  = threadIdx.x;
    const int wid  = tid >> 5;
    const int lane = tid & 31;
    const int n0   = blockIdx.x * 128;
    const int m0   = blockIdx.y * 128;

    const int mbase = (wid >> 1) * 32;   // warp m offset within CTA tile
    const int nbase = (wid & 1) * 64;    // warp n offset

    for (int i = tid; i < 128; i += 256) {
        int n = n0 + i;
        bias_s[i] = (n < Nlog) ? bias[n] : 0.f;
    }

    // per-lane ldmatrix address components
    const int rowA  = mbase + (lane & 15);
    const int colA8 = (lane >> 4) << 3;
    const int g2    = lane >> 3;
    const int rowB  = nbase + ((g2 & 2) << 2) + (lane & 7);
    const int colB8 = (g2 & 1) << 3;

    const uint32_t aAh = smem_u32(sAh), aAl = smem_u32(sAl);
    const uint32_t aBh = smem_u32(sBh), aBl = smem_u32(sBl);

    // global sources (uint4 = 8 bf16); row stride = 512/8 = 64 uint4
    const uint4* gA[2] = { (const uint4*)(Ah + (size_t)m0 * 512),
                           (const uint4*)(Al + (size_t)m0 * 512) };
    const uint4* gB[2] = { (const uint4*)(Bh + (size_t)n0 * 512),
                           (const uint4*)(Bl + (size_t)n0 * 512) };
    __nv_bfloat16* stile[4] = { sAh, sAl, sBh, sBl };

    float d[2][8][4];
#pragma unroll
    for (int i = 0; i < 2; i++)
#pragma unroll
        for (int j = 0; j < 8; j++)
#pragma unroll
            for (int q = 0; q < 4; q++) d[i][j][q] = 0.f;

    for (int kc = 0; kc < 16; ++kc) {
        if (kc) __syncthreads();
        // ---- fill 4 tiles: 128 rows x 32 bf16 each (= 4 uint4 per row) ----
#pragma unroll
        for (int it = 0; it < 8; ++it) {
            int s   = tid + it * 256;          // 0..2047
            int mat = s >> 9;
            int rem = s & 511;
            int row = rem >> 2;
            int q   = rem & 3;
            uint4 v = (mat < 2 ? gA[mat] : gB[mat - 2])[(size_t)row * 64 + kc * 4 + q];
            *(uint4*)(stile[mat] + row * TS + q * 8) = v;
        }
        __syncthreads();

        // ---- compute: 2 k16 steps x 3 split passes ----
#pragma unroll
        for (int ks = 0; ks < 2; ++ks) {
#pragma unroll
            for (int p = 0; p < 3; ++p) {
                const uint32_t baseA = (p == 2) ? aAl : aAh;
                const uint32_t baseB = (p == 1) ? aBl : aBh;
                uint32_t a[2][4], b[8][2];
#pragma unroll
                for (int mb = 0; mb < 2; ++mb)
                    ldsm4(a[mb][0], a[mb][1], a[mb][2], a[mb][3],
                          baseA + ((rowA + mb * 16) * TS + ks * 16 + colA8) * 2);
#pragma unroll
                for (int nbp = 0; nbp < 4; ++nbp)
                    ldsm4(b[2*nbp][0], b[2*nbp][1], b[2*nbp+1][0], b[2*nbp+1][1],
                          baseB + ((rowB + nbp * 16) * TS + ks * 16 + colB8) * 2);
#pragma unroll
                for (int mb = 0; mb < 2; ++mb)
#pragma unroll
                    for (int nb = 0; nb < 8; ++nb)
                        mma_bf16(d[mb][nb], a[mb], b[nb]);
            }
        }
    }

    // ---- epilogue ----
    const int gq = lane >> 2, tq = lane & 3;
#pragma unroll
    for (int mb = 0; mb < 2; ++mb) {
#pragma unroll
        for (int half = 0; half < 2; ++half) {
            int m = m0 + mbase + mb * 16 + gq + half * 8;
            float* crow;
            if (EPI == 0) crow = C + (size_t)m * Nlog;
            else          crow = C + (size_t)(m & 31) * (T_ * V_) + (size_t)(m >> 5) * V_;
#pragma unroll
            for (int nb = 0; nb < 8; ++nb) {
                int nl = nbase + nb * 8 + tq * 2;
                int n  = n0 + nl;
                if (n < Nlog) {
                    float2 o;
                    o.x = d[mb][nb][half * 2 + 0] + bias_s[nl];
                    o.y = d[mb][nb][half * 2 + 1] + bias_s[nl + 1];
                    *(float2*)&crow[n] = o;
                }
            }
        }
    }
}

// ------------------------- persistent LSTM recurrence -----------------------
#define LSTM_NCTA 128

__device__ __forceinline__ float sigmoidf_(float x) { return 1.f / (1.f + expf(-x)); }

__global__ void __launch_bounds__(256, 1)
lstm_kernel(const float* __restrict__ Whh)
{
    __shared__ float Ws[16 * 512];        // 32 KB
    __shared__ float red[4 * 16 * 32];    // 8 KB

    const int tid  = threadIdx.x;
    const int bx   = blockIdx.x;
    const int w    = tid >> 5;
    const int lane = tid & 31;

    for (int s = tid; s < 16 * 512; s += 256) {
        int jl = s >> 9, k = s & 511;
        int g  = jl >> 2;
        int jh = (bx << 2) + (jl & 3);
        Ws[s] = Whh[(size_t)(g * 512 + jh) * 512 + k];
    }

    float c_state = 0.f;
    const int jh_l    = tid >> 5;
    const int jh_glob = (bx << 2) + jh_l;
    __syncthreads();

    float hreg[64];
    float accv[16];

    for (int t = 0; t < 64; ++t) {
        if (t > 0) {
#pragma unroll
            for (int i = 0; i < 64; ++i)
                hreg[i] = __ldcg(&g_hT[(w * 64 + i) * 32 + lane]);
#pragma unroll
            for (int jl = 0; jl < 16; ++jl) {
                const float4* wv = (const float4*)&Ws[jl * 512 + w * 64];
                float a = 0.f;
#pragma unroll
                for (int q = 0; q < 16; ++q) {
                    float4 v = wv[q];
                    a += v.x * hreg[q * 4 + 0] + v.y * hreg[q * 4 + 1]
                       + v.z * hreg[q * 4 + 2] + v.w * hreg[q * 4 + 3];
                }
                accv[jl] = a;
            }
            if (w < 4) {
#pragma unroll
                for (int jl = 0; jl < 16; ++jl)
                    red[(w * 16 + jl) * 32 + lane] = accv[jl];
            }
        }
        __syncthreads();
        if (t > 0 && w >= 4) {
#pragma unroll
            for (int jl = 0; jl < 16; ++jl)
                red[((w - 4) * 16 + jl) * 32 + lane] += accv[jl];
        }
        __syncthreads();

        if (tid < 128) {
            const int b = lane;
            float gv[4];
#pragma unroll
            for (int g = 0; g < 4; ++g) {
                float s = 0.f;
                if (t > 0) {
                    int jl = g * 4 + jh_l;
#pragma unroll
                    for (int ww = 0; ww < 4; ++ww)
                        s += red[(ww * 16 + jl) * 32 + b];
                }
                gv[g] = g_Gin[(size_t)(t * 32 + b) * G_ + g * 512 + jh_glob] + s;
            }
            float i_ = sigmoidf_(gv[0]);
            float f_ = sigmoidf_(gv[1]);
            float gg = tanhf(gv[2]);
            float o_ = sigmoidf_(gv[3]);
            c_state = f_ * c_state + i_ * gg;
            float h = o_ * tanhf(c_state);
            g_hT[jh_glob * 32 + b] = h;
            __nv_bfloat16 hh = __float2bfloat16(h);
            size_t hi = (size_t)(t * 32 + b) * H_ + jh_glob;
            g_hs_h[hi] = hh;
            g_hs_l[hi] = __float2bfloat16(h - __bfloat162float(hh));
        }

        // ---- grid barrier ----
        __threadfence();
        __syncthreads();
        if (tid == 0) {
            unsigned gen = *(volatile unsigned*)&g_bargen;
            unsigned arrived = atomicAdd(&g_barcnt, 1u);
            if (arrived == LSTM_NCTA - 1) {
                g_barcnt = 0;
                __threadfence();
                atomicAdd(&g_bargen, 1u);
            } else {
                while (*(volatile unsigned*)&g_bargen == gen) { }
            }
        }
        __syncthreads();
    }
}

// ------------------------- launch ------------------------------------------
extern "C" void kernel_launch(void* const* d_in, const int* in_sizes, int n_in,
                              void* d_out, int out_size)
{
    const float* features = (const float*)d_in[0];
    const int*   captions = (const int*)d_in[1];
    // d_in[2] = forward_approach (unused)
    const float* embed = (const float*)d_in[3];
    const float* W_ih  = (const float*)d_in[4];
    const float* W_hh  = (const float*)d_in[5];
    const float* b_ih  = (const float*)d_in[6];
    const float* b_hh  = (const float*)d_in[7];
    const float* fc_W  = (const float*)d_in[8];
    const float* fc_b  = (const float*)d_in[9];
    float* out = (float*)d_out;

    float *pGin, *pbias;
    __nv_bfloat16 *pXh, *pXl, *pWih_h, *pWih_l, *pfcW_h, *pfcW_l, *phs_h, *phs_l;
    cudaGetSymbolAddress((void**)&pGin,   g_Gin);
    cudaGetSymbolAddress((void**)&pbias,  g_biasg);
    cudaGetSymbolAddress((void**)&pXh,    g_Xh);
    cudaGetSymbolAddress((void**)&pXl,    g_Xl);
    cudaGetSymbolAddress((void**)&pWih_h, g_Wih_h);
    cudaGetSymbolAddress((void**)&pWih_l, g_Wih_l);
    cudaGetSymbolAddress((void**)&pfcW_h, g_fcW_h);
    cudaGetSymbolAddress((void**)&pfcW_l, g_fcW_l);
    cudaGetSymbolAddress((void**)&phs_h,  g_hs_h);
    cudaGetSymbolAddress((void**)&phs_l,  g_hs_l);

    // 1) build split X + fused bias
    prep_kernel<<<(T_ * B_ * E_) / 256, 256>>>(features, captions, embed, b_ih, b_hh);

    // 2) split weights
    split_kernel<<<(G_ * E_ + 255) / 256, 256>>>(W_ih, pWih_h, pWih_l, G_ * E_, G_ * E_);
    split_kernel<<<(VPAD * H_ + 255) / 256, 256>>>(fc_W, pfcW_h, pfcW_l, V_ * H_, VPAD * H_);

    // 3) Gin = X @ W_ih^T + (b_ih + b_hh)   (2048 x 2048, K=512)
    mma_gemm<0><<<dim3(G_ / 128, (T_ * B_) / 128), 256>>>(
        pXh, pXl, pWih_h, pWih_l, pbias, pGin, G_);

    // 4) persistent LSTM recurrence (64 steps), writes split hs
    lstm_kernel<<<LSTM_NCTA, 256>>>(W_hh);

    // 5) logits = hs @ fc_W^T + fc_b, written as (B, T, V)
    mma_gemm<1><<<dim3(VPAD / 128, (T_ * B_) / 128), 256>>>(
        phs_h, phs_l, pfcW_h, pfcW_l, fc_b, out, V_);
}

// round 5
// speedup vs baseline: 1.6625x; 1.0031x over previous
#include <cuda_runtime.h>
#include <cuda_bf16.h>
#include <math.h>
#include <stdint.h>

#define B_  32
#define T_  64
#define E_  512
#define H_  512
#define V_  10000
#define G_  2048          // 4*H
#define VPAD 10112        // 79 * 128

// ------------------------- device scratch (no allocs allowed) ---------------
__device__ __nv_bfloat16 g_Xh  [T_ * B_ * E_];
__device__ __nv_bfloat16 g_Xl  [T_ * B_ * E_];
__device__ __nv_bfloat16 g_Wih_h[G_ * E_];
__device__ __nv_bfloat16 g_Wih_l[G_ * E_];
__device__ __nv_bfloat16 g_Whh_h[G_ * H_];
__device__ __nv_bfloat16 g_Whh_l[G_ * H_];
__device__ __nv_bfloat16 g_fcW_h[VPAD * H_];
__device__ __nv_bfloat16 g_fcW_l[VPAD * H_];
__device__ __nv_bfloat16 g_hs_h[T_ * B_ * H_];
__device__ __nv_bfloat16 g_hs_l[T_ * B_ * H_];
__device__ __nv_bfloat16 g_hb_h[B_ * H_];     // current h, b-major, split
__device__ __nv_bfloat16 g_hb_l[B_ * H_];
__device__ float g_Gin [T_ * G_ * B_];        // [t][n][b]  (n = gate row)
__device__ float g_biasg[G_];
__device__ unsigned g_barcnt;
__device__ unsigned g_bargen;

// ------------------------- helpers (baseline PTX, sm_80+) -------------------
__device__ __forceinline__ uint32_t smem_u32(const void* p) {
    uint32_t a;
    asm("{ .reg .u64 t; cvta.to.shared.u64 t, %1; cvt.u32.u64 %0, t; }"
        : "=r"(a) : "l"(p));
    return a;
}
__device__ __forceinline__ void ldsm4(uint32_t& r0, uint32_t& r1,
                                      uint32_t& r2, uint32_t& r3, uint32_t addr) {
    asm volatile("ldmatrix.sync.aligned.m8n8.x4.shared.b16 {%0,%1,%2,%3}, [%4];"
                 : "=r"(r0), "=r"(r1), "=r"(r2), "=r"(r3) : "r"(addr));
}
__device__ __forceinline__ void mma_bf16(float* d, const uint32_t* a, const uint32_t* b) {
    asm volatile(
        "mma.sync.aligned.m16n8k16.row.col.f32.bf16.bf16.f32 "
        "{%0,%1,%2,%3}, {%4,%5,%6,%7}, {%8,%9}, {%0,%1,%2,%3};"
        : "+f"(d[0]), "+f"(d[1]), "+f"(d[2]), "+f"(d[3])
        : "r"(a[0]), "r"(a[1]), "r"(a[2]), "r"(a[3]), "r"(b[0]), "r"(b[1]));
}
__device__ __forceinline__ void cpa16(uint32_t saddr, const void* g) {
    asm volatile("cp.async.cg.shared.global [%0], [%1], 16;" :: "r"(saddr), "l"(g));
}
#define CP_COMMIT() asm volatile("cp.async.commit_group;" ::: "memory")
#define CP_WAIT(n)  asm volatile("cp.async.wait_group %0;" :: "n"(n) : "memory")

// ------------------------- prep: split-X + fused bias -----------------------
__global__ void prep_kernel(const float* __restrict__ features,
                            const int* __restrict__ captions,
                            const float* __restrict__ embed,
                            const float* __restrict__ b_ih,
                            const float* __restrict__ b_hh)
{
    int idx = blockIdx.x * blockDim.x + threadIdx.x;   // T*B*E = 1,048,576
    int e = idx & (E_ - 1);
    int b = (idx >> 9) & (B_ - 1);
    int t = idx >> 14;
    float v;
    if (t == 0) {
        v = features[b * E_ + e];
    } else {
        int tok = captions[b * T_ + (t - 1)];
        tok = min(max(tok, 0), V_ - 1);
        v = embed[(size_t)tok * E_ + e];
    }
    __nv_bfloat16 h = __float2bfloat16(v);
    g_Xh[idx] = h;
    g_Xl[idx] = __float2bfloat16(v - __bfloat162float(h));
    if (idx < G_) g_biasg[idx] = b_ih[idx] + b_hh[idx];
}

// ------------------------- weight split -------------------------------------
__global__ void split_kernel(const float* __restrict__ src,
                             __nv_bfloat16* __restrict__ hi,
                             __nv_bfloat16* __restrict__ lo,
                             int n_valid, int n_pad)
{
    int i = blockIdx.x * 256 + threadIdx.x;
    if (i >= n_pad) return;
    float v = (i < n_valid) ? src[i] : 0.f;
    __nv_bfloat16 h = __float2bfloat16(v);
    hi[i] = h;
    lo[i] = __float2bfloat16(v - __bfloat162float(h));
}

// ------------------------- mma.sync GEMM with cp.async pipeline -------------
// C = A(Mx512) * B(Npadx512)^T + bias, 3-pass split bf16.
// CTA tile 128x128, 8 warps 32x64, K-chunk 32, 2-stage cp.async pipeline.
// EPI 0: Gin layout  C[(m>>5)*G_*B_ + n*B_ + (m&31)]   (= [t][n][b])
// EPI 1: FC output   C[(m&31)*T*V + (m>>5)*V + n]
#define TS 40                       // smem row stride (bf16)
#define TILE_B (128 * TS * 2)       // 10240 bytes per tile
#define STAGE_B (4 * TILE_B)        // 40960 per stage

template<int EPI>
__global__ void __launch_bounds__(256, 2)
mma_gemm(const __nv_bfloat16* __restrict__ Ah, const __nv_bfloat16* __restrict__ Al,
         const __nv_bfloat16* __restrict__ Bh, const __nv_bfloat16* __restrict__ Bl,
         const float* __restrict__ bias, float* __restrict__ C, int Nlog)
{
    extern __shared__ uint8_t dyn[];
    float* bias_s = (float*)(dyn + 2 * STAGE_B);

    const int tid  = threadIdx.x;
    const int wid  = tid >> 5;
    const int lane = tid & 31;
    const int n0   = blockIdx.x * 128;
    const int m0   = blockIdx.y * 128;

    const int mbase = (wid >> 1) * 32;
    const int nbase = (wid & 1) * 64;

    for (int i = tid; i < 128; i += 256) {
        int n = n0 + i;
        bias_s[i] = (n < Nlog) ? bias[n] : 0.f;
    }

    const int rowA  = mbase + (lane & 15);
    const int colA8 = (lane >> 4) << 3;
    const int g2    = lane >> 3;
    const int rowB  = nbase + ((g2 & 2) << 2) + (lane & 7);
    const int colB8 = (g2 & 1) << 3;

    const uint32_t sbase = smem_u32(dyn);

    const uint4* gsrc[4] = {
        (const uint4*)(Ah + (size_t)m0 * 512), (const uint4*)(Al + (size_t)m0 * 512),
        (const uint4*)(Bh + (size_t)n0 * 512), (const uint4*)(Bl + (size_t)n0 * 512) };

    // per-thread load slot (8 per thread per stage)
    float d[2][8][4];
#pragma unroll
    for (int i = 0; i < 2; i++)
#pragma unroll
        for (int j = 0; j < 8; j++)
#pragma unroll
            for (int q = 0; q < 4; q++) d[i][j][q] = 0.f;

    // prefetch kc=0 into stage 0
#pragma unroll
    for (int it = 0; it < 8; ++it) {
        int s = tid + it * 256, mat = s >> 9, rem = s & 511, row = rem >> 2, q = rem & 3;
        cpa16(sbase + mat * TILE_B + (row * TS + q * 8) * 2,
              gsrc[mat] + (size_t)row * 64 + q);
    }
    CP_COMMIT();

    for (int kc = 0; kc < 16; ++kc) {
        const int cur = kc & 1;
        if (kc < 15) {
            const uint32_t st = sbase + (cur ^ 1) * STAGE_B;
#pragma unroll
            for (int it = 0; it < 8; ++it) {
                int s = tid + it * 256, mat = s >> 9, rem = s & 511, row = rem >> 2, q = rem & 3;
                cpa16(st + mat * TILE_B + (row * TS + q * 8) * 2,
                      gsrc[mat] + (size_t)row * 64 + (kc + 1) * 4 + q);
            }
            CP_COMMIT();
            CP_WAIT(1);
        } else {
            CP_WAIT(0);
        }
        __syncthreads();

        const uint32_t aAh = sbase + cur * STAGE_B;
        const uint32_t aAl = aAh + TILE_B;
        const uint32_t aBh = aAl + TILE_B;
        const uint32_t aBl = aBh + TILE_B;
#pragma unroll
        for (int ks = 0; ks < 2; ++ks) {
#pragma unroll
            for (int p = 0; p < 3; ++p) {
                const uint32_t baseA = (p == 2) ? aAl : aAh;
                const uint32_t baseB = (p == 1) ? aBl : aBh;
                uint32_t a[2][4], b[8][2];
#pragma unroll
                for (int mb = 0; mb < 2; ++mb)
                    ldsm4(a[mb][0], a[mb][1], a[mb][2], a[mb][3],
                          baseA + ((rowA + mb * 16) * TS + ks * 16 + colA8) * 2);
#pragma unroll
                for (int nbp = 0; nbp < 4; ++nbp)
                    ldsm4(b[2*nbp][0], b[2*nbp][1], b[2*nbp+1][0], b[2*nbp+1][1],
                          baseB + ((rowB + nbp * 16) * TS + ks * 16 + colB8) * 2);
#pragma unroll
                for (int mb = 0; mb < 2; ++mb)
#pragma unroll
                    for (int nb = 0; nb < 8; ++nb)
                        mma_bf16(d[mb][nb], a[mb], b[nb]);
            }
        }
        __syncthreads();
    }

    // ---- epilogue ----
    const int gq = lane >> 2, tq = lane & 3;
#pragma unroll
    for (int mb = 0; mb < 2; ++mb) {
#pragma unroll
        for (int half = 0; half < 2; ++half) {
            int m = m0 + mbase + mb * 16 + gq + half * 8;
#pragma unroll
            for (int nb = 0; nb < 8; ++nb) {
                int nl = nbase + nb * 8 + tq * 2;
                int n  = n0 + nl;
                float v0 = d[mb][nb][half * 2 + 0] + bias_s[nl];
                float v1 = d[mb][nb][half * 2 + 1] + bias_s[nl + 1];
                if (EPI == 0) {
                    size_t base = (size_t)(m >> 5) * (G_ * B_) + (m & 31);
                    C[base + (size_t)n * B_]       = v0;
                    C[base + (size_t)(n + 1) * B_] = v1;
                } else if (n < Nlog) {
                    float* crow = C + (size_t)(m & 31) * (T_ * V_) + (size_t)(m >> 5) * V_;
                    float2 o; o.x = v0; o.y = v1;
                    *(float2*)&crow[n] = o;
                }
            }
        }
    }
}

// ------------------------- persistent LSTM on tensor cores ------------------
// 64 CTAs x 256 threads. CTA bx owns 8 hidden units jh in [bx*8, bx*8+8)
// => 32 gate rows {g*512 + bx*8 + j}. W_hh slice (split) resident in smem.
// Per step: stage h (32x512 split bf16) -> gates[32x32] = h @ Wslice^T via
// 3-pass mma.sync -> elementwise update (1 (b,jh) state per thread).
#define LNCTA 64
#define LTS 520                      // smem row stride (bf16): 512 + 8 pad
#define L_WROW (32 * LTS * 2)        // 33280 bytes per 32x520 bf16 tile
// dynamic smem offsets
#define OFF_WH 0
#define OFF_WL (OFF_WH + L_WROW)
#define OFF_AH (OFF_WL + L_WROW)
#define OFF_AL (OFF_AH + L_WROW)
#define OFF_GT (OFF_AL + L_WROW)                 // gates: 32 x 33 floats
#define LSMEM  (OFF_GT + 32 * 33 * 4)

__device__ __forceinline__ float sigmoidf_(float x) { return 1.f / (1.f + expf(-x)); }

__global__ void __launch_bounds__(256, 1)
lstm_mma_kernel()
{
    extern __shared__ uint8_t dyn[];
    float* gates = (float*)(dyn + OFF_GT);

    const int tid  = threadIdx.x;
    const int bx   = blockIdx.x;
    const int w    = tid >> 5;         // warp id = jh_local for update
    const int lane = tid & 31;         // = batch b for update

    const uint32_t sb   = smem_u32(dyn);
    const uint32_t aWH  = sb + OFF_WH;
    const uint32_t aWL  = sb + OFF_WL;
    const uint32_t aAH  = sb + OFF_AH;
    const uint32_t aAL  = sb + OFF_AL;

    // ---- load W_hh slice (32 rows x 512) split into smem, once ----
    {
        const uint4* wh = (const uint4*)g_Whh_h;
        const uint4* wl = (const uint4*)g_Whh_l;
#pragma unroll
        for (int it = 0; it < 8; ++it) {
            int idx = tid + it * 256;           // 0..2047
            int r = idx >> 6, q = idx & 63;
            int gr = (r >> 3) * 512 + bx * 8 + (r & 7);
            *(uint4*)(dyn + OFF_WH + (r * LTS + q * 8) * 2) = wh[(size_t)gr * 64 + q];
            *(uint4*)(dyn + OFF_WL + (r * LTS + q * 8) * 2) = wl[(size_t)gr * 64 + q];
        }
    }

    // mma indexing: warp w -> m-tile mt, n-tile nt
    const int mt = w & 1;
    const int nt = w >> 1;
    const int rowA  = mt * 16 + (lane & 15);
    const int colA8 = (lane >> 4) << 3;
    const int rowB  = nt * 8 + (lane & 7);
    const int colB8 = (lane >> 3) << 3;
    const int gq = lane >> 2, tq = lane & 3;

    float c_state = 0.f;
    const int jh = bx * 8 + w;
    __syncthreads();

    for (int t = 0; t < 64; ++t) {
        if (t > 0) {
            // ---- stage h (b-major, split) into smem ----
            const uint4* hh = (const uint4*)g_hb_h;
            const uint4* hl = (const uint4*)g_hb_l;
#pragma unroll
            for (int it = 0; it < 8; ++it) {
                int idx = tid + it * 256;       // 0..2047
                int b = idx >> 6, q = idx & 63;
                *(uint4*)(dyn + OFF_AH + (b * LTS + q * 8) * 2) = hh[idx];
                *(uint4*)(dyn + OFF_AL + (b * LTS + q * 8) * 2) = hl[idx];
            }
            __syncthreads();

            // ---- gates = h @ Wslice^T : 3 chains x 32 k-steps ----
            float d0[4] = {0,0,0,0}, d1[4] = {0,0,0,0}, d2[4] = {0,0,0,0};
#pragma unroll
            for (int kb = 0; kb < 16; ++kb) {
                uint32_t aH0[4], aH1[4], aL0[4], aL1[4], bH[4], bL[4];
                ldsm4(aH0[0],aH0[1],aH0[2],aH0[3], aAH + (rowA*LTS + kb*32      + colA8)*2);
                ldsm4(aH1[0],aH1[1],aH1[2],aH1[3], aAH + (rowA*LTS + kb*32 + 16 + colA8)*2);
                ldsm4(aL0[0],aL0[1],aL0[2],aL0[3], aAL + (rowA*LTS + kb*32      + colA8)*2);
                ldsm4(aL1[0],aL1[1],aL1[2],aL1[3], aAL + (rowA*LTS + kb*32 + 16 + colA8)*2);
                ldsm4(bH[0],bH[1],bH[2],bH[3],     aWH + (rowB*LTS + kb*32 + colB8)*2);
                ldsm4(bL[0],bL[1],bL[2],bL[3],     aWL + (rowB*LTS + kb*32 + colB8)*2);
                mma_bf16(d0, aH0, bH + 0);  mma_bf16(d0, aH1, bH + 2);
                mma_bf16(d1, aH0, bL + 0);  mma_bf16(d1, aH1, bL + 2);
                mma_bf16(d2, aL0, bH + 0);  mma_bf16(d2, aL1, bH + 2);
            }
            // ---- D -> gates smem ----
            {
                int r0 = mt * 16 + gq;
                int cc = nt * 8 + tq * 2;
                gates[r0 * 33 + cc]           = d0[0] + d1[0] + d2[0];
                gates[r0 * 33 + cc + 1]       = d0[1] + d1[1] + d2[1];
                gates[(r0 + 8) * 33 + cc]     = d0[2] + d1[2] + d2[2];
                gates[(r0 + 8) * 33 + cc + 1] = d0[3] + d1[3] + d2[3];
            }
        }
        __syncthreads();

        // ---- elementwise update: thread (b=lane, jh_l=w) ----
        {
            const int b = lane;
            float gv[4];
#pragma unroll
            for (int g = 0; g < 4; ++g) {
                float s = g_Gin[(size_t)t * (G_ * B_) + (size_t)(g * 512 + jh) * B_ + b];
                if (t > 0) s += gates[b * 33 + g * 8 + w];
                gv[g] = s;
            }
            float i_ = sigmoidf_(gv[0]);
            float f_ = sigmoidf_(gv[1]);
            float gg = tanhf(gv[2]);
            float o_ = sigmoidf_(gv[3]);
            c_state = f_ * c_state + i_ * gg;
            float h = o_ * tanhf(c_state);
            __nv_bfloat16 hh = __float2bfloat16(h);
            __nv_bfloat16 hl = __float2bfloat16(h - __bfloat162float(hh));
            g_hb_h[b * 512 + jh] = hh;
            g_hb_l[b * 512 + jh] = hl;
            size_t hsix = (size_t)(t * 32 + b) * H_ + jh;
            g_hs_h[hsix] = hh;
            g_hs_l[hsix] = hl;
        }

        // ---- grid barrier (64 CTAs, all co-resident) ----
        __threadfence();
        __syncthreads();
        if (tid == 0) {
            unsigned gen = *(volatile unsigned*)&g_bargen;
            unsigned arrived = atomicAdd(&g_barcnt, 1u);
            if (arrived == LNCTA - 1) {
                g_barcnt = 0;
                __threadfence();
                atomicAdd(&g_bargen, 1u);
            } else {
                while (*(volatile unsigned*)&g_bargen == gen) { }
            }
        }
        __syncthreads();
    }
}

// ------------------------- launch ------------------------------------------
extern "C" void kernel_launch(void* const* d_in, const int* in_sizes, int n_in,
                              void* d_out, int out_size)
{
    const float* features = (const float*)d_in[0];
    const int*   captions = (const int*)d_in[1];
    // d_in[2] = forward_approach (unused)
    const float* embed = (const float*)d_in[3];
    const float* W_ih  = (const float*)d_in[4];
    const float* W_hh  = (const float*)d_in[5];
    const float* b_ih  = (const float*)d_in[6];
    const float* b_hh  = (const float*)d_in[7];
    const float* fc_W  = (const float*)d_in[8];
    const float* fc_b  = (const float*)d_in[9];
    float* out = (float*)d_out;

    float *pGin, *pbias;
    __nv_bfloat16 *pXh, *pXl, *pWih_h, *pWih_l, *pWhh_h, *pWhh_l,
                  *pfcW_h, *pfcW_l, *phs_h, *phs_l;
    cudaGetSymbolAddress((void**)&pGin,   g_Gin);
    cudaGetSymbolAddress((void**)&pbias,  g_biasg);
    cudaGetSymbolAddress((void**)&pXh,    g_Xh);
    cudaGetSymbolAddress((void**)&pXl,    g_Xl);
    cudaGetSymbolAddress((void**)&pWih_h, g_Wih_h);
    cudaGetSymbolAddress((void**)&pWih_l, g_Wih_l);
    cudaGetSymbolAddress((void**)&pWhh_h, g_Whh_h);
    cudaGetSymbolAddress((void**)&pWhh_l, g_Whh_l);
    cudaGetSymbolAddress((void**)&pfcW_h, g_fcW_h);
    cudaGetSymbolAddress((void**)&pfcW_l, g_fcW_l);
    cudaGetSymbolAddress((void**)&phs_h,  g_hs_h);
    cudaGetSymbolAddress((void**)&phs_l,  g_hs_l);

    const int SMEM_GEMM = 2 * STAGE_B + 512;     // 82432
    cudaFuncSetAttribute(mma_gemm<0>, cudaFuncAttributeMaxDynamicSharedMemorySize, SMEM_GEMM);
    cudaFuncSetAttribute(mma_gemm<1>, cudaFuncAttributeMaxDynamicSharedMemorySize, SMEM_GEMM);
    cudaFuncSetAttribute(lstm_mma_kernel, cudaFuncAttributeMaxDynamicSharedMemorySize, LSMEM);

    // 1) build split X + fused bias
    prep_kernel<<<(T_ * B_ * E_) / 256, 256>>>(features, captions, embed, b_ih, b_hh);

    // 2) split weights
    split_kernel<<<(G_ * E_ + 255) / 256, 256>>>(W_ih, pWih_h, pWih_l, G_ * E_, G_ * E_);
    split_kernel<<<(G_ * H_ + 255) / 256, 256>>>(W_hh, pWhh_h, pWhh_l, G_ * H_, G_ * H_);
    split_kernel<<<(VPAD * H_ + 255) / 256, 256>>>(fc_W, pfcW_h, pfcW_l, V_ * H_, VPAD * H_);

    // 3) Gin[t][n][b] = X @ W_ih^T + (b_ih + b_hh)
    mma_gemm<0><<<dim3(G_ / 128, (T_ * B_) / 128), 256, SMEM_GEMM>>>(
        pXh, pXl, pWih_h, pWih_l, pbias, pGin, G_);

    // 4) persistent LSTM recurrence on tensor cores
    lstm_mma_kernel<<<LNCTA, 256, LSMEM>>>();

    // 5) logits = hs @ fc_W^T + fc_b, written as (B, T, V)
    mma_gemm<1><<<dim3(VPAD / 128, (T_ * B_) / 128), 256, SMEM_GEMM>>>(
        phs_h, phs_l, pfcW_h, pfcW_l, fc_b, out, V_);
}

// round 6
// speedup vs baseline: 1.8356x; 1.1041x over previous
#include <cuda_runtime.h>
#include <cuda_fp16.h>
#include <math.h>
#include <stdint.h>

#define B_  32
#define T_  64
#define E_  512
#define H_  512
#define V_  10000
#define G_  2048          // 4*H
#define VPAD 10112        // 79 * 128

// ------------------------- device scratch (no allocs allowed) ---------------
__device__ __half g_Xh  [T_ * B_ * E_];
__device__ __half g_Xl  [T_ * B_ * E_];
__device__ __half g_Wih_h[G_ * E_];
__device__ __half g_Wih_l[G_ * E_];
__device__ __half g_Whh_h[G_ * H_];
__device__ __half g_Whh_l[G_ * H_];
__device__ __half g_fcW_h[VPAD * H_];
__device__ __half g_hs_h[T_ * B_ * H_];
__device__ __half g_hs_l[T_ * B_ * H_];
__device__ __half g_hb_h[B_ * H_];     // current h, b-major, split
__device__ __half g_hb_l[B_ * H_];
__device__ float g_Gin [T_ * G_ * B_];  // [t][n][b]
__device__ float g_biasg[G_];
__device__ unsigned g_barcnt;
__device__ unsigned g_bargen;

// ------------------------- helpers (baseline PTX, sm_80+) -------------------
__device__ __forceinline__ uint32_t smem_u32(const void* p) {
    uint32_t a;
    asm("{ .reg .u64 t; cvta.to.shared.u64 t, %1; cvt.u32.u64 %0, t; }"
        : "=r"(a) : "l"(p));
    return a;
}
__device__ __forceinline__ void ldsm4(uint32_t& r0, uint32_t& r1,
                                      uint32_t& r2, uint32_t& r3, uint32_t addr) {
    asm volatile("ldmatrix.sync.aligned.m8n8.x4.shared.b16 {%0,%1,%2,%3}, [%4];"
                 : "=r"(r0), "=r"(r1), "=r"(r2), "=r"(r3) : "r"(addr));
}
__device__ __forceinline__ void mma_f16(float* d, const uint32_t* a, const uint32_t* b) {
    asm volatile(
        "mma.sync.aligned.m16n8k16.row.col.f32.f16.f16.f32 "
        "{%0,%1,%2,%3}, {%4,%5,%6,%7}, {%8,%9}, {%0,%1,%2,%3};"
        : "+f"(d[0]), "+f"(d[1]), "+f"(d[2]), "+f"(d[3])
        : "r"(a[0]), "r"(a[1]), "r"(a[2]), "r"(a[3]), "r"(b[0]), "r"(b[1]));
}
__device__ __forceinline__ void cpa16(uint32_t saddr, const void* g) {
    asm volatile("cp.async.cg.shared.global [%0], [%1], 16;" :: "r"(saddr), "l"(g));
}
#define CP_COMMIT() asm volatile("cp.async.commit_group;" ::: "memory")
#define CP_WAIT(n)  asm volatile("cp.async.wait_group %0;" :: "n"(n) : "memory")

__device__ __forceinline__ void split2h(float v, __half& hi, __half& lo) {
    __half h = __float2half(v);
    hi = h;
    lo = __float2half(v - __half2float(h));
}

// ------------------------- prep: split-X + fused bias -----------------------
__global__ void prep_kernel(const float* __restrict__ features,
                            const int* __restrict__ captions,
                            const float* __restrict__ embed,
                            const float* __restrict__ b_ih,
                            const float* __restrict__ b_hh)
{
    int idx = blockIdx.x * blockDim.x + threadIdx.x;   // T*B*E = 1,048,576
    int e = idx & (E_ - 1);
    int b = (idx >> 9) & (B_ - 1);
    int t = idx >> 14;
    float v;
    if (t == 0) {
        v = features[b * E_ + e];
    } else {
        int tok = captions[b * T_ + (t - 1)];
        tok = min(max(tok, 0), V_ - 1);
        v = embed[(size_t)tok * E_ + e];
    }
    split2h(v, g_Xh[idx], g_Xl[idx]);
    if (idx < G_) g_biasg[idx] = b_ih[idx] + b_hh[idx];
}

// ------------------------- weight split (lo optional) -----------------------
template<bool LO>
__global__ void split_kernel(const float* __restrict__ src,
                             __half* __restrict__ hi,
                             __half* __restrict__ lo,
                             int n_valid, int n_pad)
{
    int i = blockIdx.x * 256 + threadIdx.x;
    if (i >= n_pad) return;
    float v = (i < n_valid) ? src[i] : 0.f;
    __half h = __float2half(v);
    hi[i] = h;
    if (LO) lo[i] = __float2half(v - __half2float(h));
}

// ------------------------- mma.sync GEMM, fp16 split, NPASS passes ----------
// C = A(Mx512) * B(Npadx512)^T + bias
// NPASS=3: Ah*Bh + Ah*Bl + Al*Bh (tiles Ah,Al,Bh,Bl)
// NPASS=2: Ah*Bh + Al*Bh          (tiles Ah,Al,Bh; B fp16-rounded)
// CTA tile 128x128, 8 warps 32x64, K-chunk 32, 2-stage cp.async pipeline.
// EPI 0: Gin layout  C[(m>>5)*G_*B_ + n*B_ + (m&31)]
// EPI 1: FC output   C[(m&31)*T*V + (m>>5)*V + n]
#define TS 40                       // smem row stride (halves)
#define TILE_B (128 * TS * 2)       // 10240 bytes per tile

template<int EPI, int NPASS>
__global__ void __launch_bounds__(256, 2)
mma_gemm(const __half* __restrict__ Ah, const __half* __restrict__ Al,
         const __half* __restrict__ Bh, const __half* __restrict__ Bl,
         const float* __restrict__ bias, float* __restrict__ C, int Nlog)
{
    constexpr int NT = NPASS + 1;            // tiles per stage
    constexpr int STAGE = NT * TILE_B;

    extern __shared__ uint8_t dyn[];
    float* bias_s = (float*)(dyn + 2 * STAGE);

    const int tid  = threadIdx.x;
    const int wid  = tid >> 5;
    const int lane = tid & 31;
    const int n0   = blockIdx.x * 128;
    const int m0   = blockIdx.y * 128;

    const int mbase = (wid >> 1) * 32;
    const int nbase = (wid & 1) * 64;

    for (int i = tid; i < 128; i += 256) {
        int n = n0 + i;
        bias_s[i] = (n < Nlog) ? bias[n] : 0.f;
    }

    const int rowA  = mbase + (lane & 15);
    const int colA8 = (lane >> 4) << 3;
    const int g2    = lane >> 3;
    const int rowB  = nbase + ((g2 & 2) << 2) + (lane & 7);
    const int colB8 = (g2 & 1) << 3;

    const uint32_t sbase = smem_u32(dyn);

    const uint4* gsrc[NT];
    gsrc[0] = (const uint4*)(Ah + (size_t)m0 * 512);
    gsrc[1] = (const uint4*)(Al + (size_t)m0 * 512);
    gsrc[2] = (const uint4*)(Bh + (size_t)n0 * 512);
    if (NT == 4) gsrc[3] = (const uint4*)(Bl + (size_t)n0 * 512);

    float d[2][8][4];
#pragma unroll
    for (int i = 0; i < 2; i++)
#pragma unroll
        for (int j = 0; j < 8; j++)
#pragma unroll
            for (int q = 0; q < 4; q++) d[i][j][q] = 0.f;

    // prefetch kc=0 into stage 0
#pragma unroll
    for (int it = 0; it < NT * 2; ++it) {
        int s = tid + it * 256, mat = s >> 9, rem = s & 511, row = rem >> 2, q = rem & 3;
        cpa16(sbase + mat * TILE_B + (row * TS + q * 8) * 2,
              gsrc[mat] + (size_t)row * 64 + q);
    }
    CP_COMMIT();

    for (int kc = 0; kc < 16; ++kc) {
        const int cur = kc & 1;
        if (kc < 15) {
            const uint32_t st = sbase + (cur ^ 1) * STAGE;
#pragma unroll
            for (int it = 0; it < NT * 2; ++it) {
                int s = tid + it * 256, mat = s >> 9, rem = s & 511, row = rem >> 2, q = rem & 3;
                cpa16(st + mat * TILE_B + (row * TS + q * 8) * 2,
                      gsrc[mat] + (size_t)row * 64 + (kc + 1) * 4 + q);
            }
            CP_COMMIT();
            CP_WAIT(1);
        } else {
            CP_WAIT(0);
        }
        __syncthreads();

        const uint32_t aAh = sbase + cur * STAGE;
        const uint32_t aAl = aAh + TILE_B;
        const uint32_t aBh = aAl + TILE_B;
        const uint32_t aBl = aBh + TILE_B;   // valid only if NT==4
#pragma unroll
        for (int ks = 0; ks < 2; ++ks) {
#pragma unroll
            for (int p = 0; p < NPASS; ++p) {
                const uint32_t baseA = (p == NPASS - 1) ? aAl : aAh;
                const uint32_t baseB = (NPASS == 3 && p == 1) ? aBl : aBh;
                uint32_t a[2][4], b[8][2];
#pragma unroll
                for (int mb = 0; mb < 2; ++mb)
                    ldsm4(a[mb][0], a[mb][1], a[mb][2], a[mb][3],
                          baseA + ((rowA + mb * 16) * TS + ks * 16 + colA8) * 2);
#pragma unroll
                for (int nbp = 0; nbp < 4; ++nbp)
                    ldsm4(b[2*nbp][0], b[2*nbp][1], b[2*nbp+1][0], b[2*nbp+1][1],
                          baseB + ((rowB + nbp * 16) * TS + ks * 16 + colB8) * 2);
#pragma unroll
                for (int mb = 0; mb < 2; ++mb)
#pragma unroll
                    for (int nb = 0; nb < 8; ++nb)
                        mma_f16(d[mb][nb], a[mb], b[nb]);
            }
        }
        __syncthreads();
    }

    // ---- epilogue ----
    const int gq = lane >> 2, tq = lane & 3;
#pragma unroll
    for (int mb = 0; mb < 2; ++mb) {
#pragma unroll
        for (int half = 0; half < 2; ++half) {
            int m = m0 + mbase + mb * 16 + gq + half * 8;
#pragma unroll
            for (int nb = 0; nb < 8; ++nb) {
                int nl = nbase + nb * 8 + tq * 2;
                int n  = n0 + nl;
                float v0 = d[mb][nb][half * 2 + 0] + bias_s[nl];
                float v1 = d[mb][nb][half * 2 + 1] + bias_s[nl + 1];
                if (EPI == 0) {
                    size_t base = (size_t)(m >> 5) * (G_ * B_) + (m & 31);
                    C[base + (size_t)n * B_]       = v0;
                    C[base + (size_t)(n + 1) * B_] = v1;
                } else if (n < Nlog) {
                    float* crow = C + (size_t)(m & 31) * (T_ * V_) + (size_t)(m >> 5) * V_;
                    float2 o; o.x = v0; o.y = v1;
                    *(float2*)&crow[n] = o;
                }
            }
        }
    }
}

// ------------------------- persistent LSTM on tensor cores ------------------
// 64 CTAs x 256 threads. CTA bx owns 8 hidden units jh in [bx*8, bx*8+8)
// => 32 gate rows. W_hh slice (fp16 split) resident in smem.
// Per step: prefetch Gin -> stage h (32x512 fp16 split) -> gates = h@W^T
// (3-pass mma) -> elementwise update.
#define LNCTA 64
#define LTS 520
#define L_WROW (32 * LTS * 2)
#define OFF_WH 0
#define OFF_WL (OFF_WH + L_WROW)
#define OFF_AH (OFF_WL + L_WROW)
#define OFF_AL (OFF_AH + L_WROW)
#define OFF_GT (OFF_AL + L_WROW)
#define LSMEM  (OFF_GT + 32 * 33 * 4)

__device__ __forceinline__ float sigmoidf_(float x) { return 1.f / (1.f + expf(-x)); }

__global__ void __launch_bounds__(256, 1)
lstm_mma_kernel()
{
    extern __shared__ uint8_t dyn[];
    float* gates = (float*)(dyn + OFF_GT);

    const int tid  = threadIdx.x;
    const int bx   = blockIdx.x;
    const int w    = tid >> 5;
    const int lane = tid & 31;

    const uint32_t sb   = smem_u32(dyn);
    const uint32_t aWH  = sb + OFF_WH;
    const uint32_t aWL  = sb + OFF_WL;
    const uint32_t aAH  = sb + OFF_AH;
    const uint32_t aAL  = sb + OFF_AL;

    // ---- load W_hh slice (32 rows x 512) into smem, once ----
    {
        const uint4* wh = (const uint4*)g_Whh_h;
        const uint4* wl = (const uint4*)g_Whh_l;
#pragma unroll
        for (int it = 0; it < 8; ++it) {
            int idx = tid + it * 256;
            int r = idx >> 6, q = idx & 63;
            int gr = (r >> 3) * 512 + bx * 8 + (r & 7);
            *(uint4*)(dyn + OFF_WH + (r * LTS + q * 8) * 2) = wh[(size_t)gr * 64 + q];
            *(uint4*)(dyn + OFF_WL + (r * LTS + q * 8) * 2) = wl[(size_t)gr * 64 + q];
        }
    }

    const int mt = w & 1;
    const int nt = w >> 1;
    const int rowA  = mt * 16 + (lane & 15);
    const int colA8 = (lane >> 4) << 3;
    const int rowB  = nt * 8 + (lane & 7);
    const int colB8 = (lane >> 3) << 3;
    const int gq = lane >> 2, tq = lane & 3;

    float c_state = 0.f;
    const int jh = bx * 8 + w;
    __syncthreads();

    for (int t = 0; t < 64; ++t) {
        // ---- prefetch this step's Gin gate biases (no h dependency) ----
        float gpre[4];
#pragma unroll
        for (int g = 0; g < 4; ++g)
            gpre[g] = __ldcg(&g_Gin[(size_t)t * (G_ * B_)
                                    + (size_t)(g * 512 + jh) * B_ + lane]);

        if (t > 0) {
            // ---- stage h (b-major, fp16 split) into smem ----
            const uint4* hh = (const uint4*)g_hb_h;
            const uint4* hl = (const uint4*)g_hb_l;
#pragma unroll
            for (int it = 0; it < 8; ++it) {
                int idx = tid + it * 256;
                int b = idx >> 6, q = idx & 63;
                *(uint4*)(dyn + OFF_AH + (b * LTS + q * 8) * 2) = hh[idx];
                *(uint4*)(dyn + OFF_AL + (b * LTS + q * 8) * 2) = hl[idx];
            }
            __syncthreads();

            // ---- gates = h @ Wslice^T : 3 chains x 32 k-steps ----
            float d0[4] = {0,0,0,0}, d1[4] = {0,0,0,0}, d2[4] = {0,0,0,0};
#pragma unroll
            for (int kb = 0; kb < 16; ++kb) {
                uint32_t aH0[4], aH1[4], aL0[4], aL1[4], bH[4], bL[4];
                ldsm4(aH0[0],aH0[1],aH0[2],aH0[3], aAH + (rowA*LTS + kb*32      + colA8)*2);
                ldsm4(aH1[0],aH1[1],aH1[2],aH1[3], aAH + (rowA*LTS + kb*32 + 16 + colA8)*2);
                ldsm4(aL0[0],aL0[1],aL0[2],aL0[3], aAL + (rowA*LTS + kb*32      + colA8)*2);
                ldsm4(aL1[0],aL1[1],aL1[2],aL1[3], aAL + (rowA*LTS + kb*32 + 16 + colA8)*2);
                ldsm4(bH[0],bH[1],bH[2],bH[3],     aWH + (rowB*LTS + kb*32 + colB8)*2);
                ldsm4(bL[0],bL[1],bL[2],bL[3],     aWL + (rowB*LTS + kb*32 + colB8)*2);
                mma_f16(d0, aH0, bH + 0);  mma_f16(d0, aH1, bH + 2);
                mma_f16(d1, aH0, bL + 0);  mma_f16(d1, aH1, bL + 2);
                mma_f16(d2, aL0, bH + 0);  mma_f16(d2, aL1, bH + 2);
            }
            {
                int r0 = mt * 16 + gq;
                int cc = nt * 8 + tq * 2;
                gates[r0 * 33 + cc]           = d0[0] + d1[0] + d2[0];
                gates[r0 * 33 + cc + 1]       = d0[1] + d1[1] + d2[1];
                gates[(r0 + 8) * 33 + cc]     = d0[2] + d1[2] + d2[2];
                gates[(r0 + 8) * 33 + cc + 1] = d0[3] + d1[3] + d2[3];
            }
        }
        __syncthreads();

        // ---- elementwise update: thread (b=lane, jh) ----
        {
            const int b = lane;
            float gv[4];
#pragma unroll
            for (int g = 0; g < 4; ++g) {
                float s = gpre[g];
                if (t > 0) s += gates[b * 33 + g * 8 + w];
                gv[g] = s;
            }
            float i_ = sigmoidf_(gv[0]);
            float f_ = sigmoidf_(gv[1]);
            float gg = tanhf(gv[2]);
            float o_ = sigmoidf_(gv[3]);
            c_state = f_ * c_state + i_ * gg;
            float h = o_ * tanhf(c_state);
            __half hh, hl;
            split2h(h, hh, hl);
            g_hb_h[b * 512 + jh] = hh;
            g_hb_l[b * 512 + jh] = hl;
            size_t hsix = (size_t)(t * 32 + b) * H_ + jh;
            g_hs_h[hsix] = hh;
            g_hs_l[hsix] = hl;
        }

        // ---- grid barrier ----
        __threadfence();
        __syncthreads();
        if (tid == 0) {
            unsigned gen = *(volatile unsigned*)&g_bargen;
            unsigned arrived = atomicAdd(&g_barcnt, 1u);
            if (arrived == LNCTA - 1) {
                g_barcnt = 0;
                __threadfence();
                atomicAdd(&g_bargen, 1u);
            } else {
                while (*(volatile unsigned*)&g_bargen == gen) { }
            }
        }
        __syncthreads();
    }
}

// ------------------------- launch ------------------------------------------
extern "C" void kernel_launch(void* const* d_in, const int* in_sizes, int n_in,
                              void* d_out, int out_size)
{
    const float* features = (const float*)d_in[0];
    const int*   captions = (const int*)d_in[1];
    // d_in[2] = forward_approach (unused)
    const float* embed = (const float*)d_in[3];
    const float* W_ih  = (const float*)d_in[4];
    const float* W_hh  = (const float*)d_in[5];
    const float* b_ih  = (const float*)d_in[6];
    const float* b_hh  = (const float*)d_in[7];
    const float* fc_W  = (const float*)d_in[8];
    const float* fc_b  = (const float*)d_in[9];
    float* out = (float*)d_out;

    float *pGin, *pbias;
    __half *pXh, *pXl, *pWih_h, *pWih_l, *pWhh_h, *pWhh_l, *pfcW_h, *phs_h, *phs_l;
    cudaGetSymbolAddress((void**)&pGin,   g_Gin);
    cudaGetSymbolAddress((void**)&pbias,  g_biasg);
    cudaGetSymbolAddress((void**)&pXh,    g_Xh);
    cudaGetSymbolAddress((void**)&pXl,    g_Xl);
    cudaGetSymbolAddress((void**)&pWih_h, g_Wih_h);
    cudaGetSymbolAddress((void**)&pWih_l, g_Wih_l);
    cudaGetSymbolAddress((void**)&pWhh_h, g_Whh_h);
    cudaGetSymbolAddress((void**)&pWhh_l, g_Whh_l);
    cudaGetSymbolAddress((void**)&pfcW_h, g_fcW_h);
    cudaGetSymbolAddress((void**)&phs_h,  g_hs_h);
    cudaGetSymbolAddress((void**)&phs_l,  g_hs_l);

    const int SMEM_G3 = 2 * 4 * TILE_B + 512;   // 82432 (Gin, 3-pass)
    const int SMEM_G2 = 2 * 3 * TILE_B + 512;   // 61952 (FC, 2-pass)
    cudaFuncSetAttribute(mma_gemm<0,3>, cudaFuncAttributeMaxDynamicSharedMemorySize, SMEM_G3);
    cudaFuncSetAttribute(mma_gemm<1,2>, cudaFuncAttributeMaxDynamicSharedMemorySize, SMEM_G2);
    cudaFuncSetAttribute(lstm_mma_kernel, cudaFuncAttributeMaxDynamicSharedMemorySize, LSMEM);

    // 1) build split X + fused bias
    prep_kernel<<<(T_ * B_ * E_) / 256, 256>>>(features, captions, embed, b_ih, b_hh);

    // 2) split weights (fc_W hi-only)
    split_kernel<true ><<<(G_ * E_ + 255) / 256, 256>>>(W_ih, pWih_h, pWih_l, G_ * E_, G_ * E_);
    split_kernel<true ><<<(G_ * H_ + 255) / 256, 256>>>(W_hh, pWhh_h, pWhh_l, G_ * H_, G_ * H_);
    split_kernel<false><<<(VPAD * H_ + 255) / 256, 256>>>(fc_W, pfcW_h, nullptr, V_ * H_, VPAD * H_);

    // 3) Gin[t][n][b] = X @ W_ih^T + (b_ih + b_hh)   (fp16 3-pass)
    mma_gemm<0,3><<<dim3(G_ / 128, (T_ * B_) / 128), 256, SMEM_G3>>>(
        pXh, pXl, pWih_h, pWih_l, pbias, pGin, G_);

    // 4) persistent LSTM recurrence on tensor cores
    lstm_mma_kernel<<<LNCTA, 256, LSMEM>>>();

    // 5) logits = hs @ fc_W^T + fc_b   (fp16 2-pass), written as (B, T, V)
    mma_gemm<1,2><<<dim3(VPAD / 128, (T_ * B_) / 128), 256, SMEM_G2>>>(
        phs_h, phs_l, pfcW_h, nullptr, fc_b, out, V_);
}

// round 7
// speedup vs baseline: 1.9769x; 1.0770x over previous
#include <cuda_runtime.h>
#include <cuda_fp16.h>
#include <math.h>
#include <stdint.h>

#define B_  32
#define T_  64
#define E_  512
#define H_  512
#define V_  10000
#define G_  2048          // 4*H
#define VPAD 10112        // 79 * 128
#define LNCTA 64

// ------------------------- device scratch (no allocs allowed) ---------------
__device__ __half g_Xh  [T_ * B_ * E_];
__device__ __half g_Xl  [T_ * B_ * E_];
__device__ __half g_Wih_h[G_ * E_];
__device__ __half g_Wih_l[G_ * E_];
__device__ __half g_Whh_h[G_ * H_];
__device__ __half g_Whh_l[G_ * H_];
__device__ __half g_fcW_h[VPAD * H_];
__device__ __half g_hs_h[T_ * B_ * H_];
__device__ __half g_hs_l[T_ * B_ * H_];
__device__ __half g_hb_h[2][B_ * H_];     // double-buffered current h (b-major)
__device__ __half g_hb_l[2][B_ * H_];
__device__ float g_Gin [T_ * G_ * B_];    // [t][n][b]
__device__ float g_biasg[G_];
__device__ unsigned g_flags[LNCTA * 32];  // 128B-strided per-CTA step flags

// ------------------------- helpers (baseline PTX, sm_80+) -------------------
__device__ __forceinline__ uint32_t smem_u32(const void* p) {
    uint32_t a;
    asm("{ .reg .u64 t; cvta.to.shared.u64 t, %1; cvt.u32.u64 %0, t; }"
        : "=r"(a) : "l"(p));
    return a;
}
__device__ __forceinline__ void ldsm4(uint32_t& r0, uint32_t& r1,
                                      uint32_t& r2, uint32_t& r3, uint32_t addr) {
    asm volatile("ldmatrix.sync.aligned.m8n8.x4.shared.b16 {%0,%1,%2,%3}, [%4];"
                 : "=r"(r0), "=r"(r1), "=r"(r2), "=r"(r3) : "r"(addr));
}
__device__ __forceinline__ void mma_f16(float* d, const uint32_t* a, const uint32_t* b) {
    asm volatile(
        "mma.sync.aligned.m16n8k16.row.col.f32.f16.f16.f32 "
        "{%0,%1,%2,%3}, {%4,%5,%6,%7}, {%8,%9}, {%0,%1,%2,%3};"
        : "+f"(d[0]), "+f"(d[1]), "+f"(d[2]), "+f"(d[3])
        : "r"(a[0]), "r"(a[1]), "r"(a[2]), "r"(a[3]), "r"(b[0]), "r"(b[1]));
}
__device__ __forceinline__ void cpa16(uint32_t saddr, const void* g) {
    asm volatile("cp.async.cg.shared.global [%0], [%1], 16;" :: "r"(saddr), "l"(g));
}
#define CP_COMMIT() asm volatile("cp.async.commit_group;" ::: "memory")
#define CP_WAIT(n)  asm volatile("cp.async.wait_group %0;" :: "n"(n) : "memory")

__device__ __forceinline__ unsigned ld_acq(const unsigned* p) {
    unsigned v;
    asm volatile("ld.acquire.gpu.u32 %0, [%1];" : "=r"(v) : "l"(p) : "memory");
    return v;
}
__device__ __forceinline__ void st_rel(unsigned* p, unsigned v) {
    asm volatile("st.release.gpu.u32 [%0], %1;" :: "l"(p), "r"(v) : "memory");
}
__device__ __forceinline__ void split2h(float v, __half& hi, __half& lo) {
    __half h = __float2half(v);
    hi = h;
    lo = __float2half(v - __half2float(h));
}
__device__ __forceinline__ uint32_t h2u(__half2 h) {
    return *reinterpret_cast<uint32_t*>(&h);
}

// ------------------------- prep: split-X (vectorized) + bias + flag reset ---
__global__ void prep_kernel(const float4* __restrict__ features4,
                            const int* __restrict__ captions,
                            const float4* __restrict__ embed4,
                            const float4* __restrict__ b_ih4,
                            const float4* __restrict__ b_hh4)
{
    int i = blockIdx.x * blockDim.x + threadIdx.x;   // over T*B*E/4 = 262,144
    int e4 = i & 127;               // float4 index within 512-wide row
    int b  = (i >> 7) & (B_ - 1);
    int t  = i >> 12;
    float4 v;
    if (t == 0) {
        v = features4[b * 128 + e4];
    } else {
        int tok = captions[b * T_ + (t - 1)];
        tok = min(max(tok, 0), V_ - 1);
        v = embed4[(size_t)tok * 128 + e4];
    }
    __half2 h0 = __floats2half2_rn(v.x, v.y);
    __half2 h1 = __floats2half2_rn(v.z, v.w);
    float2 r0 = __half22float2(h0), r1 = __half22float2(h1);
    __half2 l0 = __floats2half2_rn(v.x - r0.x, v.y - r0.y);
    __half2 l1 = __floats2half2_rn(v.z - r1.x, v.w - r1.y);
    ((uint2*)g_Xh)[i] = make_uint2(h2u(h0), h2u(h1));
    ((uint2*)g_Xl)[i] = make_uint2(h2u(l0), h2u(l1));
    if (i < G_ / 4) {
        float4 a = b_ih4[i], c = b_hh4[i];
        ((float4*)g_biasg)[i] = make_float4(a.x + c.x, a.y + c.y, a.z + c.z, a.w + c.w);
    }
    if (i < LNCTA * 32) g_flags[i] = 0;   // reset barrier flags for this launch
}

// ------------------------- weight split (vectorized, lo optional) -----------
template<bool LO>
__global__ void split_kernel(const float4* __restrict__ src,
                             uint2* __restrict__ hi, uint2* __restrict__ lo,
                             int n4_valid, int n4_pad)
{
    int i = blockIdx.x * 256 + threadIdx.x;
    if (i >= n4_pad) return;
    float4 v = (i < n4_valid) ? src[i] : make_float4(0.f, 0.f, 0.f, 0.f);
    __half2 h0 = __floats2half2_rn(v.x, v.y);
    __half2 h1 = __floats2half2_rn(v.z, v.w);
    hi[i] = make_uint2(h2u(h0), h2u(h1));
    if (LO) {
        float2 r0 = __half22float2(h0), r1 = __half22float2(h1);
        __half2 l0 = __floats2half2_rn(v.x - r0.x, v.y - r0.y);
        __half2 l1 = __floats2half2_rn(v.z - r1.x, v.w - r1.y);
        lo[i] = make_uint2(h2u(l0), h2u(l1));
    }
}

// ------------------------- mma.sync GEMM (unchanged from R6) ----------------
#define TS 40
#define TILE_B (128 * TS * 2)

template<int EPI, int NPASS>
__global__ void __launch_bounds__(256, 2)
mma_gemm(const __half* __restrict__ Ah, const __half* __restrict__ Al,
         const __half* __restrict__ Bh, const __half* __restrict__ Bl,
         const float* __restrict__ bias, float* __restrict__ C, int Nlog)
{
    constexpr int NT = NPASS + 1;
    constexpr int STAGE = NT * TILE_B;

    extern __shared__ uint8_t dyn[];
    float* bias_s = (float*)(dyn + 2 * STAGE);

    const int tid  = threadIdx.x;
    const int wid  = tid >> 5;
    const int lane = tid & 31;
    const int n0   = blockIdx.x * 128;
    const int m0   = blockIdx.y * 128;

    const int mbase = (wid >> 1) * 32;
    const int nbase = (wid & 1) * 64;

    for (int i = tid; i < 128; i += 256) {
        int n = n0 + i;
        bias_s[i] = (n < Nlog) ? bias[n] : 0.f;
    }

    const int rowA  = mbase + (lane & 15);
    const int colA8 = (lane >> 4) << 3;
    const int g2    = lane >> 3;
    const int rowB  = nbase + ((g2 & 2) << 2) + (lane & 7);
    const int colB8 = (g2 & 1) << 3;

    const uint32_t sbase = smem_u32(dyn);

    const uint4* gsrc[NT];
    gsrc[0] = (const uint4*)(Ah + (size_t)m0 * 512);
    gsrc[1] = (const uint4*)(Al + (size_t)m0 * 512);
    gsrc[2] = (const uint4*)(Bh + (size_t)n0 * 512);
    if (NT == 4) gsrc[3] = (const uint4*)(Bl + (size_t)n0 * 512);

    float d[2][8][4];
#pragma unroll
    for (int i = 0; i < 2; i++)
#pragma unroll
        for (int j = 0; j < 8; j++)
#pragma unroll
            for (int q = 0; q < 4; q++) d[i][j][q] = 0.f;

#pragma unroll
    for (int it = 0; it < NT * 2; ++it) {
        int s = tid + it * 256, mat = s >> 9, rem = s & 511, row = rem >> 2, q = rem & 3;
        cpa16(sbase + mat * TILE_B + (row * TS + q * 8) * 2,
              gsrc[mat] + (size_t)row * 64 + q);
    }
    CP_COMMIT();

    for (int kc = 0; kc < 16; ++kc) {
        const int cur = kc & 1;
        if (kc < 15) {
            const uint32_t st = sbase + (cur ^ 1) * STAGE;
#pragma unroll
            for (int it = 0; it < NT * 2; ++it) {
                int s = tid + it * 256, mat = s >> 9, rem = s & 511, row = rem >> 2, q = rem & 3;
                cpa16(st + mat * TILE_B + (row * TS + q * 8) * 2,
                      gsrc[mat] + (size_t)row * 64 + (kc + 1) * 4 + q);
            }
            CP_COMMIT();
            CP_WAIT(1);
        } else {
            CP_WAIT(0);
        }
        __syncthreads();

        const uint32_t aAh = sbase + cur * STAGE;
        const uint32_t aAl = aAh + TILE_B;
        const uint32_t aBh = aAl + TILE_B;
        const uint32_t aBl = aBh + TILE_B;
#pragma unroll
        for (int ks = 0; ks < 2; ++ks) {
#pragma unroll
            for (int p = 0; p < NPASS; ++p) {
                const uint32_t baseA = (p == NPASS - 1) ? aAl : aAh;
                const uint32_t baseB = (NPASS == 3 && p == 1) ? aBl : aBh;
                uint32_t a[2][4], b[8][2];
#pragma unroll
                for (int mb = 0; mb < 2; ++mb)
                    ldsm4(a[mb][0], a[mb][1], a[mb][2], a[mb][3],
                          baseA + ((rowA + mb * 16) * TS + ks * 16 + colA8) * 2);
#pragma unroll
                for (int nbp = 0; nbp < 4; ++nbp)
                    ldsm4(b[2*nbp][0], b[2*nbp][1], b[2*nbp+1][0], b[2*nbp+1][1],
                          baseB + ((rowB + nbp * 16) * TS + ks * 16 + colB8) * 2);
#pragma unroll
                for (int mb = 0; mb < 2; ++mb)
#pragma unroll
                    for (int nb = 0; nb < 8; ++nb)
                        mma_f16(d[mb][nb], a[mb], b[nb]);
            }
        }
        __syncthreads();
    }

    const int gq = lane >> 2, tq = lane & 3;
#pragma unroll
    for (int mb = 0; mb < 2; ++mb) {
#pragma unroll
        for (int half = 0; half < 2; ++half) {
            int m = m0 + mbase + mb * 16 + gq + half * 8;
#pragma unroll
            for (int nb = 0; nb < 8; ++nb) {
                int nl = nbase + nb * 8 + tq * 2;
                int n  = n0 + nl;
                float v0 = d[mb][nb][half * 2 + 0] + bias_s[nl];
                float v1 = d[mb][nb][half * 2 + 1] + bias_s[nl + 1];
                if (EPI == 0) {
                    size_t base = (size_t)(m >> 5) * (G_ * B_) + (m & 31);
                    C[base + (size_t)n * B_]       = v0;
                    C[base + (size_t)(n + 1) * B_] = v1;
                } else if (n < Nlog) {
                    float* crow = C + (size_t)(m & 31) * (T_ * V_) + (size_t)(m >> 5) * V_;
                    float2 o; o.x = v0; o.y = v1;
                    *(float2*)&crow[n] = o;
                }
            }
        }
    }
}

// ------------------------- persistent LSTM, fast flag barrier ---------------
// 64 CTAs x 256 threads. CTA bx owns 8 hidden units (32 gate rows).
// Per step: Gin prefetch -> flag-barrier -> cp.async h stage -> 3-pass mma
// -> elementwise update -> release flag. h double-buffered (write t&1,
// read (t-1)&1) so writer/reader never touch the same buffer in a window.
#define LTS 520
#define L_WROW (32 * LTS * 2)
#define OFF_WH 0
#define OFF_WL (OFF_WH + L_WROW)
#define OFF_AH (OFF_WL + L_WROW)
#define OFF_AL (OFF_AH + L_WROW)
#define OFF_GT (OFF_AL + L_WROW)
#define LSMEM  (OFF_GT + 32 * 33 * 4)

__device__ __forceinline__ float sigmoidf_(float x) { return 1.f / (1.f + expf(-x)); }

__global__ void __launch_bounds__(256, 1)
lstm_mma_kernel()
{
    extern __shared__ uint8_t dyn[];
    float* gates = (float*)(dyn + OFF_GT);

    const int tid  = threadIdx.x;
    const int bx   = blockIdx.x;
    const int w    = tid >> 5;
    const int lane = tid & 31;

    const uint32_t sb  = smem_u32(dyn);
    const uint32_t aWH = sb + OFF_WH;
    const uint32_t aWL = sb + OFF_WL;
    const uint32_t aAH = sb + OFF_AH;
    const uint32_t aAL = sb + OFF_AL;

    // ---- load W_hh slice (32 rows x 512, split) into smem once ----
    {
        const uint4* wh = (const uint4*)g_Whh_h;
        const uint4* wl = (const uint4*)g_Whh_l;
#pragma unroll
        for (int it = 0; it < 8; ++it) {
            int idx = tid + it * 256;
            int r = idx >> 6, q = idx & 63;
            int gr = (r >> 3) * 512 + bx * 8 + (r & 7);
            cpa16(aWH + (r * LTS + q * 8) * 2, wh + (size_t)gr * 64 + q);
            cpa16(aWL + (r * LTS + q * 8) * 2, wl + (size_t)gr * 64 + q);
        }
        CP_COMMIT();
        CP_WAIT(0);
    }

    const int mt = w & 1;
    const int nt = w >> 1;
    const int rowA  = mt * 16 + (lane & 15);
    const int colA8 = (lane >> 4) << 3;
    const int rowB  = nt * 8 + (lane & 7);
    const int colB8 = (lane >> 3) << 3;
    const int gq = lane >> 2, tq = lane & 3;

    float c_state = 0.f;
    const int jh = bx * 8 + w;
    __syncthreads();

    for (int t = 0; t < 64; ++t) {
        // ---- prefetch this step's Gin gate biases (independent of h) ----
        float gpre[4];
#pragma unroll
        for (int g = 0; g < 4; ++g)
            gpre[g] = __ldcg(&g_Gin[(size_t)t * (G_ * B_)
                                    + (size_t)(g * 512 + jh) * B_ + lane]);

        if (t > 0) {
            // ---- flag barrier: all CTAs must have published step t ----
            if (tid < LNCTA) {
                while (ld_acq(&g_flags[tid * 32]) < (unsigned)t) { }
            }
            __syncthreads();

            // ---- stage h buf[(t-1)&1] via cp.async ----
            const uint4* hh = (const uint4*)g_hb_h[(t - 1) & 1];
            const uint4* hl = (const uint4*)g_hb_l[(t - 1) & 1];
#pragma unroll
            for (int it = 0; it < 8; ++it) {
                int idx = tid + it * 256;
                int b = idx >> 6, q = idx & 63;
                cpa16(aAH + (b * LTS + q * 8) * 2, hh + idx);
                cpa16(aAL + (b * LTS + q * 8) * 2, hl + idx);
            }
            CP_COMMIT();
            CP_WAIT(0);
            __syncthreads();

            // ---- gates = h @ Wslice^T : 3 chains x 32 k-steps ----
            float d0[4] = {0,0,0,0}, d1[4] = {0,0,0,0}, d2[4] = {0,0,0,0};
#pragma unroll
            for (int kb = 0; kb < 16; ++kb) {
                uint32_t aH0[4], aH1[4], aL0[4], aL1[4], bH[4], bL[4];
                ldsm4(aH0[0],aH0[1],aH0[2],aH0[3], aAH + (rowA*LTS + kb*32      + colA8)*2);
                ldsm4(aH1[0],aH1[1],aH1[2],aH1[3], aAH + (rowA*LTS + kb*32 + 16 + colA8)*2);
                ldsm4(aL0[0],aL0[1],aL0[2],aL0[3], aAL + (rowA*LTS + kb*32      + colA8)*2);
                ldsm4(aL1[0],aL1[1],aL1[2],aL1[3], aAL + (rowA*LTS + kb*32 + 16 + colA8)*2);
                ldsm4(bH[0],bH[1],bH[2],bH[3],     aWH + (rowB*LTS + kb*32 + colB8)*2);
                ldsm4(bL[0],bL[1],bL[2],bL[3],     aWL + (rowB*LTS + kb*32 + colB8)*2);
                mma_f16(d0, aH0, bH + 0);  mma_f16(d0, aH1, bH + 2);
                mma_f16(d1, aH0, bL + 0);  mma_f16(d1, aH1, bL + 2);
                mma_f16(d2, aL0, bH + 0);  mma_f16(d2, aL1, bH + 2);
            }
            {
                int r0 = mt * 16 + gq;
                int cc = nt * 8 + tq * 2;
                gates[r0 * 33 + cc]           = d0[0] + d1[0] + d2[0];
                gates[r0 * 33 + cc + 1]       = d0[1] + d1[1] + d2[1];
                gates[(r0 + 8) * 33 + cc]     = d0[2] + d1[2] + d2[2];
                gates[(r0 + 8) * 33 + cc + 1] = d0[3] + d1[3] + d2[3];
            }
        }
        __syncthreads();

        // ---- elementwise update: thread (b=lane, jh) ----
        {
            const int b = lane;
            float gv[4];
#pragma unroll
            for (int g = 0; g < 4; ++g) {
                float s = gpre[g];
                if (t > 0) s += gates[b * 33 + g * 8 + w];
                gv[g] = s;
            }
            float i_ = sigmoidf_(gv[0]);
            float f_ = sigmoidf_(gv[1]);
            float gg = tanhf(gv[2]);
            float o_ = sigmoidf_(gv[3]);
            c_state = f_ * c_state + i_ * gg;
            float h = o_ * tanhf(c_state);
            __half hh, hl;
            split2h(h, hh, hl);
            g_hb_h[t & 1][b * 512 + jh] = hh;
            g_hb_l[t & 1][b * 512 + jh] = hl;
            size_t hsix = (size_t)(t * 32 + b) * H_ + jh;
            g_hs_h[hsix] = hh;
            g_hs_l[hsix] = hl;
        }

        // ---- publish step completion (skip after final step) ----
        if (t < 63) {
            __syncthreads();
            if (tid == 0) st_rel(&g_flags[bx * 32], (unsigned)(t + 1));
        }
    }
}

// ------------------------- launch ------------------------------------------
extern "C" void kernel_launch(void* const* d_in, const int* in_sizes, int n_in,
                              void* d_out, int out_size)
{
    const float* features = (const float*)d_in[0];
    const int*   captions = (const int*)d_in[1];
    // d_in[2] = forward_approach (unused)
    const float* embed = (const float*)d_in[3];
    const float* W_ih  = (const float*)d_in[4];
    const float* W_hh  = (const float*)d_in[5];
    const float* b_ih  = (const float*)d_in[6];
    const float* b_hh  = (const float*)d_in[7];
    const float* fc_W  = (const float*)d_in[8];
    const float* fc_b  = (const float*)d_in[9];
    float* out = (float*)d_out;

    float *pGin, *pbias;
    __half *pXh, *pXl, *pWih_h, *pWih_l, *pWhh_h, *pWhh_l, *pfcW_h, *phs_h, *phs_l;
    cudaGetSymbolAddress((void**)&pGin,   g_Gin);
    cudaGetSymbolAddress((void**)&pbias,  g_biasg);
    cudaGetSymbolAddress((void**)&pXh,    g_Xh);
    cudaGetSymbolAddress((void**)&pXl,    g_Xl);
    cudaGetSymbolAddress((void**)&pWih_h, g_Wih_h);
    cudaGetSymbolAddress((void**)&pWih_l, g_Wih_l);
    cudaGetSymbolAddress((void**)&pWhh_h, g_Whh_h);
    cudaGetSymbolAddress((void**)&pWhh_l, g_Whh_l);
    cudaGetSymbolAddress((void**)&pfcW_h, g_fcW_h);
    cudaGetSymbolAddress((void**)&phs_h,  g_hs_h);
    cudaGetSymbolAddress((void**)&phs_l,  g_hs_l);

    const int SMEM_G3 = 2 * 4 * TILE_B + 512;
    const int SMEM_G2 = 2 * 3 * TILE_B + 512;
    cudaFuncSetAttribute(mma_gemm<0,3>, cudaFuncAttributeMaxDynamicSharedMemorySize, SMEM_G3);
    cudaFuncSetAttribute(mma_gemm<1,2>, cudaFuncAttributeMaxDynamicSharedMemorySize, SMEM_G2);
    cudaFuncSetAttribute(lstm_mma_kernel, cudaFuncAttributeMaxDynamicSharedMemorySize, LSMEM);

    // 1) build split X + fused bias + reset barrier flags
    prep_kernel<<<(T_ * B_ * E_ / 4) / 256, 256>>>(
        (const float4*)features, captions, (const float4*)embed,
        (const float4*)b_ih, (const float4*)b_hh);

    // 2) split weights (vectorized; fc_W hi-only)
    split_kernel<true ><<<(G_ * E_ / 4 + 255) / 256, 256>>>(
        (const float4*)W_ih, (uint2*)pWih_h, (uint2*)pWih_l, G_ * E_ / 4, G_ * E_ / 4);
    split_kernel<true ><<<(G_ * H_ / 4 + 255) / 256, 256>>>(
        (const float4*)W_hh, (uint2*)pWhh_h, (uint2*)pWhh_l, G_ * H_ / 4, G_ * H_ / 4);
    split_kernel<false><<<(VPAD * H_ / 4 + 255) / 256, 256>>>(
        (const float4*)fc_W, (uint2*)pfcW_h, nullptr, V_ * H_ / 4, VPAD * H_ / 4);

    // 3) Gin[t][n][b] = X @ W_ih^T + (b_ih + b_hh)   (fp16 3-pass)
    mma_gemm<0,3><<<dim3(G_ / 128, (T_ * B_) / 128), 256, SMEM_G3>>>(
        pXh, pXl, pWih_h, pWih_l, pbias, pGin, G_);

    // 4) persistent LSTM recurrence (flag barrier, double-buffered h)
    lstm_mma_kernel<<<LNCTA, 256, LSMEM>>>();

    // 5) logits = hs @ fc_W^T + fc_b   (fp16 2-pass), written as (B, T, V)
    mma_gemm<1,2><<<dim3(VPAD / 128, (T_ * B_) / 128), 256, SMEM_G2>>>(
        phs_h, phs_l, pfcW_h, nullptr, fc_b, out, V_);
}

// round 8
// speedup vs baseline: 2.3558x; 1.1917x over previous
#include <cuda_runtime.h>
#include <cuda_fp16.h>
#include <math.h>
#include <stdint.h>

#define B_  32
#define T_  64
#define E_  512
#define H_  512
#define V_  10000
#define G_  2048          // 4*H
#define VPAD 10112        // 79 * 128
#define LNCTA 64          // LSTM CTAs
#define FNCTA 79          // FC worker CTAs (one 128-col tile each)

// ------------------------- device scratch (no allocs allowed) ---------------
__device__ __half g_Xh  [T_ * B_ * E_];
__device__ __half g_Xl  [T_ * B_ * E_];
__device__ __half g_Wih_h[G_ * E_];
__device__ __half g_Wih_l[G_ * E_];
__device__ __half g_Whh_h[G_ * H_];
__device__ __half g_Whh_l[G_ * H_];
__device__ __half g_fcW_h[VPAD * H_];
__device__ __half g_hs_h[T_ * B_ * H_];
__device__ __half g_hs_l[T_ * B_ * H_];
__device__ __half g_hb_h[2][B_ * H_];     // double-buffered current h (b-major)
__device__ __half g_hb_l[2][B_ * H_];
__device__ float g_Gin [T_ * G_ * B_];    // [t][n][b]
__device__ float g_biasg[G_];
__device__ unsigned g_flags[LNCTA * 32];  // 128B-strided per-CTA step flags

// ------------------------- helpers (baseline PTX, sm_80+) -------------------
__device__ __forceinline__ uint32_t smem_u32(const void* p) {
    uint32_t a;
    asm("{ .reg .u64 t; cvta.to.shared.u64 t, %1; cvt.u32.u64 %0, t; }"
        : "=r"(a) : "l"(p));
    return a;
}
__device__ __forceinline__ void ldsm4(uint32_t& r0, uint32_t& r1,
                                      uint32_t& r2, uint32_t& r3, uint32_t addr) {
    asm volatile("ldmatrix.sync.aligned.m8n8.x4.shared.b16 {%0,%1,%2,%3}, [%4];"
                 : "=r"(r0), "=r"(r1), "=r"(r2), "=r"(r3) : "r"(addr));
}
__device__ __forceinline__ void mma_f16(float* d, const uint32_t* a, const uint32_t* b) {
    asm volatile(
        "mma.sync.aligned.m16n8k16.row.col.f32.f16.f16.f32 "
        "{%0,%1,%2,%3}, {%4,%5,%6,%7}, {%8,%9}, {%0,%1,%2,%3};"
        : "+f"(d[0]), "+f"(d[1]), "+f"(d[2]), "+f"(d[3])
        : "r"(a[0]), "r"(a[1]), "r"(a[2]), "r"(a[3]), "r"(b[0]), "r"(b[1]));
}
__device__ __forceinline__ void cpa16(uint32_t saddr, const void* g) {
    asm volatile("cp.async.cg.shared.global [%0], [%1], 16;" :: "r"(saddr), "l"(g));
}
#define CP_COMMIT() asm volatile("cp.async.commit_group;" ::: "memory")
#define CP_WAIT(n)  asm volatile("cp.async.wait_group %0;" :: "n"(n) : "memory")

__device__ __forceinline__ unsigned ld_acq(const unsigned* p) {
    unsigned v;
    asm volatile("ld.acquire.gpu.u32 %0, [%1];" : "=r"(v) : "l"(p) : "memory");
    return v;
}
__device__ __forceinline__ void st_rel(unsigned* p, unsigned v) {
    asm volatile("st.release.gpu.u32 [%0], %1;" :: "l"(p), "r"(v) : "memory");
}
__device__ __forceinline__ void split2h(float v, __half& hi, __half& lo) {
    __half h = __float2half(v);
    hi = h;
    lo = __float2half(v - __half2float(h));
}
__device__ __forceinline__ uint32_t h2u(__half2 h) {
    return *reinterpret_cast<uint32_t*>(&h);
}
__device__ __forceinline__ float sigmoidf_(float x) { return 1.f / (1.f + expf(-x)); }

// ------------------------- prep: split-X (vectorized) + bias + flag reset ---
__global__ void prep_kernel(const float4* __restrict__ features4,
                            const int* __restrict__ captions,
                            const float4* __restrict__ embed4,
                            const float4* __restrict__ b_ih4,
                            const float4* __restrict__ b_hh4)
{
    int i = blockIdx.x * blockDim.x + threadIdx.x;   // over T*B*E/4 = 262,144
    int e4 = i & 127;
    int b  = (i >> 7) & (B_ - 1);
    int t  = i >> 12;
    float4 v;
    if (t == 0) {
        v = features4[b * 128 + e4];
    } else {
        int tok = captions[b * T_ + (t - 1)];
        tok = min(max(tok, 0), V_ - 1);
        v = embed4[(size_t)tok * 128 + e4];
    }
    __half2 h0 = __floats2half2_rn(v.x, v.y);
    __half2 h1 = __floats2half2_rn(v.z, v.w);
    float2 r0 = __half22float2(h0), r1 = __half22float2(h1);
    __half2 l0 = __floats2half2_rn(v.x - r0.x, v.y - r0.y);
    __half2 l1 = __floats2half2_rn(v.z - r1.x, v.w - r1.y);
    ((uint2*)g_Xh)[i] = make_uint2(h2u(h0), h2u(h1));
    ((uint2*)g_Xl)[i] = make_uint2(h2u(l0), h2u(l1));
    if (i < G_ / 4) {
        float4 a = b_ih4[i], c = b_hh4[i];
        ((float4*)g_biasg)[i] = make_float4(a.x + c.x, a.y + c.y, a.z + c.z, a.w + c.w);
    }
    if (i < LNCTA * 32) g_flags[i] = 0;
}

// ------------------------- weight split (vectorized, lo optional) -----------
template<bool LO>
__global__ void split_kernel(const float4* __restrict__ src,
                             uint2* __restrict__ hi, uint2* __restrict__ lo,
                             int n4_valid, int n4_pad)
{
    int i = blockIdx.x * 256 + threadIdx.x;
    if (i >= n4_pad) return;
    float4 v = (i < n4_valid) ? src[i] : make_float4(0.f, 0.f, 0.f, 0.f);
    __half2 h0 = __floats2half2_rn(v.x, v.y);
    __half2 h1 = __floats2half2_rn(v.z, v.w);
    hi[i] = make_uint2(h2u(h0), h2u(h1));
    if (LO) {
        float2 r0 = __half22float2(h0), r1 = __half22float2(h1);
        __half2 l0 = __floats2half2_rn(v.x - r0.x, v.y - r0.y);
        __half2 l1 = __floats2half2_rn(v.z - r1.x, v.w - r1.y);
        lo[i] = make_uint2(h2u(l0), h2u(l1));
    }
}

// ------------------------- Gin GEMM (fp16 3-pass, cp.async pipelined) -------
#define TS 40
#define TILE_B (128 * TS * 2)

__global__ void __launch_bounds__(256, 2)
gin_gemm(const __half* __restrict__ Ah, const __half* __restrict__ Al,
         const __half* __restrict__ Bh, const __half* __restrict__ Bl,
         const float* __restrict__ bias, float* __restrict__ C)
{
    constexpr int NT = 4;
    constexpr int STAGE = NT * TILE_B;

    extern __shared__ uint8_t dyn[];
    float* bias_s = (float*)(dyn + 2 * STAGE);

    const int tid  = threadIdx.x;
    const int wid  = tid >> 5;
    const int lane = tid & 31;
    const int n0   = blockIdx.x * 128;
    const int m0   = blockIdx.y * 128;

    const int mbase = (wid >> 1) * 32;
    const int nbase = (wid & 1) * 64;

    for (int i = tid; i < 128; i += 256) bias_s[i] = bias[n0 + i];

    const int rowA  = mbase + (lane & 15);
    const int colA8 = (lane >> 4) << 3;
    const int g2    = lane >> 3;
    const int rowB  = nbase + ((g2 & 2) << 2) + (lane & 7);
    const int colB8 = (g2 & 1) << 3;

    const uint32_t sbase = smem_u32(dyn);

    const uint4* gsrc[4] = {
        (const uint4*)(Ah + (size_t)m0 * 512), (const uint4*)(Al + (size_t)m0 * 512),
        (const uint4*)(Bh + (size_t)n0 * 512), (const uint4*)(Bl + (size_t)n0 * 512) };

    float d[2][8][4];
#pragma unroll
    for (int i = 0; i < 2; i++)
#pragma unroll
        for (int j = 0; j < 8; j++)
#pragma unroll
            for (int q = 0; q < 4; q++) d[i][j][q] = 0.f;

#pragma unroll
    for (int it = 0; it < 8; ++it) {
        int s = tid + it * 256, mat = s >> 9, rem = s & 511, row = rem >> 2, q = rem & 3;
        cpa16(sbase + mat * TILE_B + (row * TS + q * 8) * 2,
              gsrc[mat] + (size_t)row * 64 + q);
    }
    CP_COMMIT();

    for (int kc = 0; kc < 16; ++kc) {
        const int cur = kc & 1;
        if (kc < 15) {
            const uint32_t st = sbase + (cur ^ 1) * STAGE;
#pragma unroll
            for (int it = 0; it < 8; ++it) {
                int s = tid + it * 256, mat = s >> 9, rem = s & 511, row = rem >> 2, q = rem & 3;
                cpa16(st + mat * TILE_B + (row * TS + q * 8) * 2,
                      gsrc[mat] + (size_t)row * 64 + (kc + 1) * 4 + q);
            }
            CP_COMMIT();
            CP_WAIT(1);
        } else {
            CP_WAIT(0);
        }
        __syncthreads();

        const uint32_t aAh = sbase + cur * STAGE;
        const uint32_t aAl = aAh + TILE_B;
        const uint32_t aBh = aAl + TILE_B;
        const uint32_t aBl = aBh + TILE_B;
#pragma unroll
        for (int ks = 0; ks < 2; ++ks) {
#pragma unroll
            for (int p = 0; p < 3; ++p) {
                const uint32_t baseA = (p == 2) ? aAl : aAh;
                const uint32_t baseB = (p == 1) ? aBl : aBh;
                uint32_t a[2][4], b[8][2];
#pragma unroll
                for (int mb = 0; mb < 2; ++mb)
                    ldsm4(a[mb][0], a[mb][1], a[mb][2], a[mb][3],
                          baseA + ((rowA + mb * 16) * TS + ks * 16 + colA8) * 2);
#pragma unroll
                for (int nbp = 0; nbp < 4; ++nbp)
                    ldsm4(b[2*nbp][0], b[2*nbp][1], b[2*nbp+1][0], b[2*nbp+1][1],
                          baseB + ((rowB + nbp * 16) * TS + ks * 16 + colB8) * 2);
#pragma unroll
                for (int mb = 0; mb < 2; ++mb)
#pragma unroll
                    for (int nb = 0; nb < 8; ++nb)
                        mma_f16(d[mb][nb], a[mb], b[nb]);
            }
        }
        __syncthreads();
    }

    const int gq = lane >> 2, tq = lane & 3;
#pragma unroll
    for (int mb = 0; mb < 2; ++mb) {
#pragma unroll
        for (int half = 0; half < 2; ++half) {
            int m = m0 + mbase + mb * 16 + gq + half * 8;
#pragma unroll
            for (int nb = 0; nb < 8; ++nb) {
                int nl = nbase + nb * 8 + tq * 2;
                int n  = n0 + nl;
                size_t base = (size_t)(m >> 5) * (G_ * B_) + (m & 31);
                C[base + (size_t)n * B_]       = d[mb][nb][half * 2 + 0] + bias_s[nl];
                C[base + (size_t)(n + 1) * B_] = d[mb][nb][half * 2 + 1] + bias_s[nl + 1];
            }
        }
    }
}

// ------------------------- fused persistent LSTM + FC -----------------------
// Grid = 143 CTAs x 256 threads, all co-resident (1 CTA/SM, 200KB smem).
//  CTAs [0,64):    LSTM (as R7); publishes flag t+1 after EVERY step t.
//  CTAs [64,143):  FC worker j = bx-64 owns out cols [j*128, j*128+128).
//                  fc_W tile resident in smem; per t: acquire flags ->
//                  cp.async hs[t] -> 2-pass mma -> store out[b][t][n]+bias.
#define LTS 520
#define L_WROW (32 * LTS * 2)
#define OFF_WH 0
#define OFF_WL (OFF_WH + L_WROW)
#define OFF_AH (OFF_WL + L_WROW)
#define OFF_AL (OFF_AH + L_WROW)
#define OFF_GT (OFF_AL + L_WROW)
#define LSMEM  (OFF_GT + 32 * 33 * 4)
// FC layout (same dynamic buffer)
#define FTS 520
#define OFF_FB   0
#define FB_BYTES (128 * FTS * 2)            // 133120
#define OFF_FAH  (OFF_FB + FB_BYTES)        // A hi 32x520
#define OFF_FAL  (OFF_FAH + 32 * FTS * 2)
#define OFF_FBS  (OFF_FAL + 32 * FTS * 2)   // bias 128 floats
#define FSMEM    (OFF_FBS + 512)            // 200192
#define FUSED_SMEM (FSMEM > LSMEM ? FSMEM : LSMEM)

__global__ void __launch_bounds__(256, 1)
fused_lstm_fc(const float* __restrict__ fc_b, float* __restrict__ out)
{
    extern __shared__ uint8_t dyn[];
    const int tid  = threadIdx.x;
    const int bx   = blockIdx.x;
    const int w    = tid >> 5;
    const int lane = tid & 31;
    const uint32_t sb = smem_u32(dyn);

    if (bx < LNCTA) {
        // =================== LSTM role ===================
        float* gates = (float*)(dyn + OFF_GT);
        const uint32_t aWH = sb + OFF_WH;
        const uint32_t aWL = sb + OFF_WL;
        const uint32_t aAH = sb + OFF_AH;
        const uint32_t aAL = sb + OFF_AL;

        {
            const uint4* wh = (const uint4*)g_Whh_h;
            const uint4* wl = (const uint4*)g_Whh_l;
#pragma unroll
            for (int it = 0; it < 8; ++it) {
                int idx = tid + it * 256;
                int r = idx >> 6, q = idx & 63;
                int gr = (r >> 3) * 512 + bx * 8 + (r & 7);
                cpa16(aWH + (r * LTS + q * 8) * 2, wh + (size_t)gr * 64 + q);
                cpa16(aWL + (r * LTS + q * 8) * 2, wl + (size_t)gr * 64 + q);
            }
            CP_COMMIT();
            CP_WAIT(0);
        }

        const int mt = w & 1;
        const int nt = w >> 1;
        const int rowA  = mt * 16 + (lane & 15);
        const int colA8 = (lane >> 4) << 3;
        const int rowB  = nt * 8 + (lane & 7);
        const int colB8 = (lane >> 3) << 3;
        const int gq = lane >> 2, tq = lane & 3;

        float c_state = 0.f;
        const int jh = bx * 8 + w;
        __syncthreads();

        for (int t = 0; t < 64; ++t) {
            float gpre[4];
#pragma unroll
            for (int g = 0; g < 4; ++g)
                gpre[g] = __ldcg(&g_Gin[(size_t)t * (G_ * B_)
                                        + (size_t)(g * 512 + jh) * B_ + lane]);

            if (t > 0) {
                if (tid < LNCTA) {
                    while (ld_acq(&g_flags[tid * 32]) < (unsigned)t) { }
                }
                __syncthreads();

                const uint4* hh = (const uint4*)g_hb_h[(t - 1) & 1];
                const uint4* hl = (const uint4*)g_hb_l[(t - 1) & 1];
#pragma unroll
                for (int it = 0; it < 8; ++it) {
                    int idx = tid + it * 256;
                    int b = idx >> 6, q = idx & 63;
                    cpa16(aAH + (b * LTS + q * 8) * 2, hh + idx);
                    cpa16(aAL + (b * LTS + q * 8) * 2, hl + idx);
                }
                CP_COMMIT();
                CP_WAIT(0);
                __syncthreads();

                float d0[4] = {0,0,0,0}, d1[4] = {0,0,0,0}, d2[4] = {0,0,0,0};
#pragma unroll
                for (int kb = 0; kb < 16; ++kb) {
                    uint32_t aH0[4], aH1[4], aL0[4], aL1[4], bH[4], bL[4];
                    ldsm4(aH0[0],aH0[1],aH0[2],aH0[3], aAH + (rowA*LTS + kb*32      + colA8)*2);
                    ldsm4(aH1[0],aH1[1],aH1[2],aH1[3], aAH + (rowA*LTS + kb*32 + 16 + colA8)*2);
                    ldsm4(aL0[0],aL0[1],aL0[2],aL0[3], aAL + (rowA*LTS + kb*32      + colA8)*2);
                    ldsm4(aL1[0],aL1[1],aL1[2],aL1[3], aAL + (rowA*LTS + kb*32 + 16 + colA8)*2);
                    ldsm4(bH[0],bH[1],bH[2],bH[3],     aWH + (rowB*LTS + kb*32 + colB8)*2);
                    ldsm4(bL[0],bL[1],bL[2],bL[3],     aWL + (rowB*LTS + kb*32 + colB8)*2);
                    mma_f16(d0, aH0, bH + 0);  mma_f16(d0, aH1, bH + 2);
                    mma_f16(d1, aH0, bL + 0);  mma_f16(d1, aH1, bL + 2);
                    mma_f16(d2, aL0, bH + 0);  mma_f16(d2, aL1, bH + 2);
                }
                {
                    int r0 = mt * 16 + gq;
                    int cc = nt * 8 + tq * 2;
                    gates[r0 * 33 + cc]           = d0[0] + d1[0] + d2[0];
                    gates[r0 * 33 + cc + 1]       = d0[1] + d1[1] + d2[1];
                    gates[(r0 + 8) * 33 + cc]     = d0[2] + d1[2] + d2[2];
                    gates[(r0 + 8) * 33 + cc + 1] = d0[3] + d1[3] + d2[3];
                }
            }
            __syncthreads();

            {
                const int b = lane;
                float gv[4];
#pragma unroll
                for (int g = 0; g < 4; ++g) {
                    float s = gpre[g];
                    if (t > 0) s += gates[b * 33 + g * 8 + w];
                    gv[g] = s;
                }
                float i_ = sigmoidf_(gv[0]);
                float f_ = sigmoidf_(gv[1]);
                float gg = tanhf(gv[2]);
                float o_ = sigmoidf_(gv[3]);
                c_state = f_ * c_state + i_ * gg;
                float h = o_ * tanhf(c_state);
                __half hh, hl;
                split2h(h, hh, hl);
                g_hb_h[t & 1][b * 512 + jh] = hh;
                g_hb_l[t & 1][b * 512 + jh] = hl;
                size_t hsix = (size_t)(t * 32 + b) * H_ + jh;
                g_hs_h[hsix] = hh;
                g_hs_l[hsix] = hl;
            }

            // publish step completion (every step — FC workers need t=63 too)
            __syncthreads();
            if (tid == 0) st_rel(&g_flags[bx * 32], (unsigned)(t + 1));
        }
    } else {
        // =================== FC worker role ===================
        const int j = bx - LNCTA;            // 0..78
        const int n0 = j * 128;
        float* bias_s = (float*)(dyn + OFF_FBS);
        const uint32_t aFB = sb + OFF_FB;
        const uint32_t aAH = sb + OFF_FAH;
        const uint32_t aAL = sb + OFF_FAL;

        // resident fc_W tile: 128 rows x 512 halves
        {
            const uint4* fw = (const uint4*)g_fcW_h;
#pragma unroll
            for (int it = 0; it < 32; ++it) {
                int idx = tid + it * 256;        // 0..8191
                int r = idx >> 6, q = idx & 63;
                cpa16(aFB + (r * FTS + q * 8) * 2, fw + (size_t)(n0 + r) * 64 + q);
            }
            CP_COMMIT();
        }
        for (int i = tid; i < 128; i += 256) {
            int n = n0 + i;
            bias_s[i] = (n < V_) ? fc_b[n] : 0.f;
        }
        CP_WAIT(0);
        __syncthreads();

        // per-warp fragment addressing: warp w owns n16 = w*16, full m=32
        const int rowA  = lane & 15;
        const int colA8 = (lane >> 4) << 3;
        const int g2    = lane >> 3;
        const int rowB  = w * 16 + ((g2 & 2) << 2) + (lane & 7);
        const int colB8 = (g2 & 1) << 3;
        const int gq = lane >> 2, tq = lane & 3;

        for (int t = 0; t < 64; ++t) {
            // wait for all LSTM CTAs to publish step t
            if (tid < LNCTA) {
                while (ld_acq(&g_flags[tid * 32]) < (unsigned)(t + 1)) { }
            }
            __syncthreads();

            // stage hs[t] (32 x 512, hi+lo)
            {
                const uint4* hh = (const uint4*)(g_hs_h + (size_t)t * 32 * 512);
                const uint4* hl = (const uint4*)(g_hs_l + (size_t)t * 32 * 512);
#pragma unroll
                for (int it = 0; it < 8; ++it) {
                    int idx = tid + it * 256;
                    int b = idx >> 6, q = idx & 63;
                    cpa16(aAH + (b * FTS + q * 8) * 2, hh + idx);
                    cpa16(aAL + (b * FTS + q * 8) * 2, hl + idx);
                }
                CP_COMMIT();
                CP_WAIT(0);
                __syncthreads();
            }

            // 2-pass mma: out32x16 = (Ah + Al) @ Btile^T
            float d[2][2][4];
#pragma unroll
            for (int i = 0; i < 2; i++)
#pragma unroll
                for (int jn = 0; jn < 2; jn++)
#pragma unroll
                    for (int q = 0; q < 4; q++) d[i][jn][q] = 0.f;
#pragma unroll
            for (int kb = 0; kb < 32; ++kb) {
                uint32_t aH[2][4], aL[2][4], b[2][2];
                ldsm4(aH[0][0],aH[0][1],aH[0][2],aH[0][3], aAH + ((rowA     )*FTS + kb*16 + colA8)*2);
                ldsm4(aH[1][0],aH[1][1],aH[1][2],aH[1][3], aAH + ((rowA + 16)*FTS + kb*16 + colA8)*2);
                ldsm4(aL[0][0],aL[0][1],aL[0][2],aL[0][3], aAL + ((rowA     )*FTS + kb*16 + colA8)*2);
                ldsm4(aL[1][0],aL[1][1],aL[1][2],aL[1][3], aAL + ((rowA + 16)*FTS + kb*16 + colA8)*2);
                ldsm4(b[0][0], b[0][1], b[1][0], b[1][1],  aFB + (rowB*FTS + kb*16 + colB8)*2);
#pragma unroll
                for (int mb = 0; mb < 2; ++mb)
#pragma unroll
                    for (int nb = 0; nb < 2; ++nb) {
                        mma_f16(d[mb][nb], aH[mb], b[nb]);
                        mma_f16(d[mb][nb], aL[mb], b[nb]);
                    }
            }

            // epilogue: rows m = b (0..31), out[b][t][n]
#pragma unroll
            for (int mb = 0; mb < 2; ++mb) {
#pragma unroll
                for (int half = 0; half < 2; ++half) {
                    int b = mb * 16 + gq + half * 8;
                    float* crow = out + (size_t)b * (T_ * V_) + (size_t)t * V_;
#pragma unroll
                    for (int nb = 0; nb < 2; ++nb) {
                        int nl = w * 16 + nb * 8 + tq * 2;
                        int n  = n0 + nl;
                        if (n < V_) {
                            float2 o;
                            o.x = d[mb][nb][half * 2 + 0] + bias_s[nl];
                            o.y = d[mb][nb][half * 2 + 1] + bias_s[nl + 1];
                            *(float2*)&crow[n] = o;
                        }
                    }
                }
            }
            __syncthreads();   // done with A smem before next t overwrites
        }
    }
}

// ------------------------- launch ------------------------------------------
extern "C" void kernel_launch(void* const* d_in, const int* in_sizes, int n_in,
                              void* d_out, int out_size)
{
    const float* features = (const float*)d_in[0];
    const int*   captions = (const int*)d_in[1];
    // d_in[2] = forward_approach (unused)
    const float* embed = (const float*)d_in[3];
    const float* W_ih  = (const float*)d_in[4];
    const float* W_hh  = (const float*)d_in[5];
    const float* b_ih  = (const float*)d_in[6];
    const float* b_hh  = (const float*)d_in[7];
    const float* fc_W  = (const float*)d_in[8];
    const float* fc_b  = (const float*)d_in[9];
    float* out = (float*)d_out;

    float *pGin, *pbias;
    __half *pXh, *pXl, *pWih_h, *pWih_l, *pWhh_h, *pWhh_l, *pfcW_h;
    cudaGetSymbolAddress((void**)&pGin,   g_Gin);
    cudaGetSymbolAddress((void**)&pbias,  g_biasg);
    cudaGetSymbolAddress((void**)&pXh,    g_Xh);
    cudaGetSymbolAddress((void**)&pXl,    g_Xl);
    cudaGetSymbolAddress((void**)&pWih_h, g_Wih_h);
    cudaGetSymbolAddress((void**)&pWih_l, g_Wih_l);
    cudaGetSymbolAddress((void**)&pWhh_h, g_Whh_h);
    cudaGetSymbolAddress((void**)&pWhh_l, g_Whh_l);
    cudaGetSymbolAddress((void**)&pfcW_h, g_fcW_h);

    const int SMEM_G3 = 2 * 4 * TILE_B + 512;
    cudaFuncSetAttribute(gin_gemm, cudaFuncAttributeMaxDynamicSharedMemorySize, SMEM_G3);
    cudaFuncSetAttribute(fused_lstm_fc, cudaFuncAttributeMaxDynamicSharedMemorySize, FUSED_SMEM);

    // 1) build split X + fused bias + reset barrier flags
    prep_kernel<<<(T_ * B_ * E_ / 4) / 256, 256>>>(
        (const float4*)features, captions, (const float4*)embed,
        (const float4*)b_ih, (const float4*)b_hh);

    // 2) split weights (vectorized; fc_W hi-only)
    split_kernel<true ><<<(G_ * E_ / 4 + 255) / 256, 256>>>(
        (const float4*)W_ih, (uint2*)pWih_h, (uint2*)pWih_l, G_ * E_ / 4, G_ * E_ / 4);
    split_kernel<true ><<<(G_ * H_ / 4 + 255) / 256, 256>>>(
        (const float4*)W_hh, (uint2*)pWhh_h, (uint2*)pWhh_l, G_ * H_ / 4, G_ * H_ / 4);
    split_kernel<false><<<(VPAD * H_ / 4 + 255) / 256, 256>>>(
        (const float4*)fc_W, (uint2*)pfcW_h, nullptr, V_ * H_ / 4, VPAD * H_ / 4);

    // 3) Gin[t][n][b] = X @ W_ih^T + (b_ih + b_hh)   (fp16 3-pass)
    gin_gemm<<<dim3(G_ / 128, (T_ * B_) / 128), 256, SMEM_G3>>>(
        pXh, pXl, pWih_h, pWih_l, pbias, pGin);

    // 4) fused persistent LSTM + FC (143 CTAs, all co-resident)
    fused_lstm_fc<<<LNCTA + FNCTA, 256, FUSED_SMEM>>>(fc_b, out);
}

// round 9
// speedup vs baseline: 2.3979x; 1.0179x over previous
#include <cuda_runtime.h>
#include <cuda_fp16.h>
#include <math.h>
#include <stdint.h>

#define B_  32
#define T_  64
#define E_  512
#define H_  512
#define V_  10000
#define G_  2048          // 4*H
#define VPAD 10112        // 79 * 128
#define LNCTA 64          // LSTM CTAs
#define FNCTA 79          // FC worker CTAs (one 128-col tile each)

// ------------------------- device scratch (no allocs allowed) ---------------
__device__ __half g_Xh  [T_ * B_ * E_];
__device__ __half g_Xl  [T_ * B_ * E_];
__device__ __half g_Wih_h[G_ * E_];
__device__ __half g_Wih_l[G_ * E_];
__device__ __half g_Whh_h[G_ * H_];
__device__ __half g_Whh_l[G_ * H_];
__device__ __half g_fcW_h[VPAD * H_];
__device__ __half g_hs_h[T_ * B_ * H_];
__device__ __half g_hs_l[T_ * B_ * H_];
__device__ __half g_hb_h[2][B_ * H_];     // double-buffered current h (b-major)
__device__ __half g_hb_l[2][B_ * H_];
__device__ float g_Gin [T_ * G_ * B_];    // [t][n][b]
__device__ float g_biasg[G_];
__device__ unsigned g_flags[LNCTA * 32];  // 128B-strided per-CTA step flags

// ------------------------- helpers (baseline PTX, sm_80+) -------------------
__device__ __forceinline__ uint32_t smem_u32(const void* p) {
    uint32_t a;
    asm("{ .reg .u64 t; cvta.to.shared.u64 t, %1; cvt.u32.u64 %0, t; }"
        : "=r"(a) : "l"(p));
    return a;
}
__device__ __forceinline__ void ldsm4(uint32_t& r0, uint32_t& r1,
                                      uint32_t& r2, uint32_t& r3, uint32_t addr) {
    asm volatile("ldmatrix.sync.aligned.m8n8.x4.shared.b16 {%0,%1,%2,%3}, [%4];"
                 : "=r"(r0), "=r"(r1), "=r"(r2), "=r"(r3) : "r"(addr));
}
__device__ __forceinline__ void mma_f16(float* d, const uint32_t* a, const uint32_t* b) {
    asm volatile(
        "mma.sync.aligned.m16n8k16.row.col.f32.f16.f16.f32 "
        "{%0,%1,%2,%3}, {%4,%5,%6,%7}, {%8,%9}, {%0,%1,%2,%3};"
        : "+f"(d[0]), "+f"(d[1]), "+f"(d[2]), "+f"(d[3])
        : "r"(a[0]), "r"(a[1]), "r"(a[2]), "r"(a[3]), "r"(b[0]), "r"(b[1]));
}
__device__ __forceinline__ void cpa16(uint32_t saddr, const void* g) {
    asm volatile("cp.async.cg.shared.global [%0], [%1], 16;" :: "r"(saddr), "l"(g));
}
#define CP_COMMIT() asm volatile("cp.async.commit_group;" ::: "memory")
#define CP_WAIT(n)  asm volatile("cp.async.wait_group %0;" :: "n"(n) : "memory")

__device__ __forceinline__ unsigned ld_acq(const unsigned* p) {
    unsigned v;
    asm volatile("ld.acquire.gpu.u32 %0, [%1];" : "=r"(v) : "l"(p) : "memory");
    return v;
}
__device__ __forceinline__ void st_rel(unsigned* p, unsigned v) {
    asm volatile("st.release.gpu.u32 [%0], %1;" :: "l"(p), "r"(v) : "memory");
}
// wait with backoff: poll one producer CTA's flag until >= target
__device__ __forceinline__ void wait_flag(int q, unsigned target) {
    while (ld_acq(&g_flags[q * 32]) < target) { __nanosleep(32); }
}
__device__ __forceinline__ void split2h(float v, __half& hi, __half& lo) {
    __half h = __float2half(v);
    hi = h;
    lo = __float2half(v - __half2float(h));
}
__device__ __forceinline__ uint32_t h2u(__half2 h) {
    return *reinterpret_cast<uint32_t*>(&h);
}
__device__ __forceinline__ float sigmoidf_(float x) { return 1.f / (1.f + expf(-x)); }

// ------------------------- prep: split-X (vectorized) + bias + flag reset ---
__global__ void prep_kernel(const float4* __restrict__ features4,
                            const int* __restrict__ captions,
                            const float4* __restrict__ embed4,
                            const float4* __restrict__ b_ih4,
                            const float4* __restrict__ b_hh4)
{
    int i = blockIdx.x * blockDim.x + threadIdx.x;   // over T*B*E/4 = 262,144
    int e4 = i & 127;
    int b  = (i >> 7) & (B_ - 1);
    int t  = i >> 12;
    float4 v;
    if (t == 0) {
        v = features4[b * 128 + e4];
    } else {
        int tok = captions[b * T_ + (t - 1)];
        tok = min(max(tok, 0), V_ - 1);
        v = embed4[(size_t)tok * 128 + e4];
    }
    __half2 h0 = __floats2half2_rn(v.x, v.y);
    __half2 h1 = __floats2half2_rn(v.z, v.w);
    float2 r0 = __half22float2(h0), r1 = __half22float2(h1);
    __half2 l0 = __floats2half2_rn(v.x - r0.x, v.y - r0.y);
    __half2 l1 = __floats2half2_rn(v.z - r1.x, v.w - r1.y);
    ((uint2*)g_Xh)[i] = make_uint2(h2u(h0), h2u(h1));
    ((uint2*)g_Xl)[i] = make_uint2(h2u(l0), h2u(l1));
    if (i < G_ / 4) {
        float4 a = b_ih4[i], c = b_hh4[i];
        ((float4*)g_biasg)[i] = make_float4(a.x + c.x, a.y + c.y, a.z + c.z, a.w + c.w);
    }
    if (i < LNCTA * 32) g_flags[i] = 0;
}

// ------------------------- weight split (vectorized, lo optional) -----------
template<bool LO>
__global__ void split_kernel(const float4* __restrict__ src,
                             uint2* __restrict__ hi, uint2* __restrict__ lo,
                             int n4_valid, int n4_pad)
{
    int i = blockIdx.x * 256 + threadIdx.x;
    if (i >= n4_pad) return;
    float4 v = (i < n4_valid) ? src[i] : make_float4(0.f, 0.f, 0.f, 0.f);
    __half2 h0 = __floats2half2_rn(v.x, v.y);
    __half2 h1 = __floats2half2_rn(v.z, v.w);
    hi[i] = make_uint2(h2u(h0), h2u(h1));
    if (LO) {
        float2 r0 = __half22float2(h0), r1 = __half22float2(h1);
        __half2 l0 = __floats2half2_rn(v.x - r0.x, v.y - r0.y);
        __half2 l1 = __floats2half2_rn(v.z - r1.x, v.w - r1.y);
        lo[i] = make_uint2(h2u(l0), h2u(l1));
    }
}

// ------------------------- Gin GEMM (fp16 3-pass, cp.async pipelined) -------
#define TS 40
#define TILE_B (128 * TS * 2)

__global__ void __launch_bounds__(256, 2)
gin_gemm(const __half* __restrict__ Ah, const __half* __restrict__ Al,
         const __half* __restrict__ Bh, const __half* __restrict__ Bl,
         const float* __restrict__ bias, float* __restrict__ C)
{
    constexpr int NT = 4;
    constexpr int STAGE = NT * TILE_B;

    extern __shared__ uint8_t dyn[];
    float* bias_s = (float*)(dyn + 2 * STAGE);

    const int tid  = threadIdx.x;
    const int wid  = tid >> 5;
    const int lane = tid & 31;
    const int n0   = blockIdx.x * 128;
    const int m0   = blockIdx.y * 128;

    const int mbase = (wid >> 1) * 32;
    const int nbase = (wid & 1) * 64;

    for (int i = tid; i < 128; i += 256) bias_s[i] = bias[n0 + i];

    const int rowA  = mbase + (lane & 15);
    const int colA8 = (lane >> 4) << 3;
    const int g2    = lane >> 3;
    const int rowB  = nbase + ((g2 & 2) << 2) + (lane & 7);
    const int colB8 = (g2 & 1) << 3;

    const uint32_t sbase = smem_u32(dyn);

    const uint4* gsrc[4] = {
        (const uint4*)(Ah + (size_t)m0 * 512), (const uint4*)(Al + (size_t)m0 * 512),
        (const uint4*)(Bh + (size_t)n0 * 512), (const uint4*)(Bl + (size_t)n0 * 512) };

    float d[2][8][4];
#pragma unroll
    for (int i = 0; i < 2; i++)
#pragma unroll
        for (int j = 0; j < 8; j++)
#pragma unroll
            for (int q = 0; q < 4; q++) d[i][j][q] = 0.f;

#pragma unroll
    for (int it = 0; it < 8; ++it) {
        int s = tid + it * 256, mat = s >> 9, rem = s & 511, row = rem >> 2, q = rem & 3;
        cpa16(sbase + mat * TILE_B + (row * TS + q * 8) * 2,
              gsrc[mat] + (size_t)row * 64 + q);
    }
    CP_COMMIT();

    for (int kc = 0; kc < 16; ++kc) {
        const int cur = kc & 1;
        if (kc < 15) {
            const uint32_t st = sbase + (cur ^ 1) * STAGE;
#pragma unroll
            for (int it = 0; it < 8; ++it) {
                int s = tid + it * 256, mat = s >> 9, rem = s & 511, row = rem >> 2, q = rem & 3;
                cpa16(st + mat * TILE_B + (row * TS + q * 8) * 2,
                      gsrc[mat] + (size_t)row * 64 + (kc + 1) * 4 + q);
            }
            CP_COMMIT();
            CP_WAIT(1);
        } else {
            CP_WAIT(0);
        }
        __syncthreads();

        const uint32_t aAh = sbase + cur * STAGE;
        const uint32_t aAl = aAh + TILE_B;
        const uint32_t aBh = aAl + TILE_B;
        const uint32_t aBl = aBh + TILE_B;
#pragma unroll
        for (int ks = 0; ks < 2; ++ks) {
#pragma unroll
            for (int p = 0; p < 3; ++p) {
                const uint32_t baseA = (p == 2) ? aAl : aAh;
                const uint32_t baseB = (p == 1) ? aBl : aBh;
                uint32_t a[2][4], b[8][2];
#pragma unroll
                for (int mb = 0; mb < 2; ++mb)
                    ldsm4(a[mb][0], a[mb][1], a[mb][2], a[mb][3],
                          baseA + ((rowA + mb * 16) * TS + ks * 16 + colA8) * 2);
#pragma unroll
                for (int nbp = 0; nbp < 4; ++nbp)
                    ldsm4(b[2*nbp][0], b[2*nbp][1], b[2*nbp+1][0], b[2*nbp+1][1],
                          baseB + ((rowB + nbp * 16) * TS + ks * 16 + colB8) * 2);
#pragma unroll
                for (int mb = 0; mb < 2; ++mb)
#pragma unroll
                    for (int nb = 0; nb < 8; ++nb)
                        mma_f16(d[mb][nb], a[mb], b[nb]);
            }
        }
        __syncthreads();
    }

    const int gq = lane >> 2, tq = lane & 3;
#pragma unroll
    for (int mb = 0; mb < 2; ++mb) {
#pragma unroll
        for (int half = 0; half < 2; ++half) {
            int m = m0 + mbase + mb * 16 + gq + half * 8;
#pragma unroll
            for (int nb = 0; nb < 8; ++nb) {
                int nl = nbase + nb * 8 + tq * 2;
                int n  = n0 + nl;
                size_t base = (size_t)(m >> 5) * (G_ * B_) + (m & 31);
                C[base + (size_t)n * B_]       = d[mb][nb][half * 2 + 0] + bias_s[nl];
                C[base + (size_t)(n + 1) * B_] = d[mb][nb][half * 2 + 1] + bias_s[nl + 1];
            }
        }
    }
}

// ------------------------- fused persistent LSTM + FC -----------------------
// Grid = 143 CTAs x 256 threads, all co-resident (1 CTA/SM).
//  CTAs [0,64):    LSTM; publishes flag t+1 after every step t.
//  CTAs [64,143):  FC worker j owns out cols [j*128, j*128+128).
// Dataflow sync: each staging thread's uint4 slice (q = tid & 63) comes from
// exactly ONE producer CTA q, so it waits only on flag[q] (with nanosleep
// backoff) and stages immediately — no all-to-all barrier on the chain.
#define LTS 520
#define L_WROW (32 * LTS * 2)
#define OFF_WH 0
#define OFF_WL (OFF_WH + L_WROW)
#define OFF_AH (OFF_WL + L_WROW)
#define OFF_AL (OFF_AH + L_WROW)
#define OFF_GT (OFF_AL + L_WROW)
#define LSMEM  (OFF_GT + 32 * 33 * 4)
// FC layout (same dynamic buffer)
#define FTS 520
#define OFF_FB   0
#define FB_BYTES (128 * FTS * 2)            // 133120
#define OFF_FAH  (OFF_FB + FB_BYTES)
#define OFF_FAL  (OFF_FAH + 32 * FTS * 2)
#define OFF_FBS  (OFF_FAL + 32 * FTS * 2)
#define FSMEM    (OFF_FBS + 512)            // 200192
#define FUSED_SMEM (FSMEM > LSMEM ? FSMEM : LSMEM)

__global__ void __launch_bounds__(256, 1)
fused_lstm_fc(const float* __restrict__ fc_b, float* __restrict__ out)
{
    extern __shared__ uint8_t dyn[];
    const int tid  = threadIdx.x;
    const int bx   = blockIdx.x;
    const int w    = tid >> 5;
    const int lane = tid & 31;
    const uint32_t sb = smem_u32(dyn);
    const int srcq = tid & 63;          // producer CTA for this thread's slice

    if (bx < LNCTA) {
        // =================== LSTM role ===================
        float* gates = (float*)(dyn + OFF_GT);
        const uint32_t aWH = sb + OFF_WH;
        const uint32_t aWL = sb + OFF_WL;
        const uint32_t aAH = sb + OFF_AH;
        const uint32_t aAL = sb + OFF_AL;

        {
            const uint4* wh = (const uint4*)g_Whh_h;
            const uint4* wl = (const uint4*)g_Whh_l;
#pragma unroll
            for (int it = 0; it < 8; ++it) {
                int idx = tid + it * 256;
                int r = idx >> 6, q = idx & 63;
                int gr = (r >> 3) * 512 + bx * 8 + (r & 7);
                cpa16(aWH + (r * LTS + q * 8) * 2, wh + (size_t)gr * 64 + q);
                cpa16(aWL + (r * LTS + q * 8) * 2, wl + (size_t)gr * 64 + q);
            }
            CP_COMMIT();
            CP_WAIT(0);
        }

        const int mt = w & 1;
        const int nt = w >> 1;
        const int rowA  = mt * 16 + (lane & 15);
        const int colA8 = (lane >> 4) << 3;
        const int rowB  = nt * 8 + (lane & 7);
        const int colB8 = (lane >> 3) << 3;
        const int gq = lane >> 2, tq = lane & 3;

        float c_state = 0.f;
        const int jh = bx * 8 + w;
        __syncthreads();

        for (int t = 0; t < 64; ++t) {
            float gpre[4];
#pragma unroll
            for (int g = 0; g < 4; ++g)
                gpre[g] = __ldcg(&g_Gin[(size_t)t * (G_ * B_)
                                        + (size_t)(g * 512 + jh) * B_ + lane]);

            if (t > 0) {
                // ---- dataflow staging: wait only on my producer, then stage ----
                wait_flag(srcq, (unsigned)t);
                const uint4* hh = (const uint4*)g_hb_h[(t - 1) & 1];
                const uint4* hl = (const uint4*)g_hb_l[(t - 1) & 1];
#pragma unroll
                for (int it = 0; it < 8; ++it) {
                    int idx = tid + it * 256;          // = b*64 + srcq
                    int b = idx >> 6;
                    cpa16(aAH + (b * LTS + srcq * 8) * 2, hh + idx);
                    cpa16(aAL + (b * LTS + srcq * 8) * 2, hl + idx);
                }
                CP_COMMIT();
                CP_WAIT(0);
                __syncthreads();

                float d0[4] = {0,0,0,0}, d1[4] = {0,0,0,0}, d2[4] = {0,0,0,0};
#pragma unroll
                for (int kb = 0; kb < 16; ++kb) {
                    uint32_t aH0[4], aH1[4], aL0[4], aL1[4], bH[4], bL[4];
                    ldsm4(aH0[0],aH0[1],aH0[2],aH0[3], aAH + (rowA*LTS + kb*32      + colA8)*2);
                    ldsm4(aH1[0],aH1[1],aH1[2],aH1[3], aAH + (rowA*LTS + kb*32 + 16 + colA8)*2);
                    ldsm4(aL0[0],aL0[1],aL0[2],aL0[3], aAL + (rowA*LTS + kb*32      + colA8)*2);
                    ldsm4(aL1[0],aL1[1],aL1[2],aL1[3], aAL + (rowA*LTS + kb*32 + 16 + colA8)*2);
                    ldsm4(bH[0],bH[1],bH[2],bH[3],     aWH + (rowB*LTS + kb*32 + colB8)*2);
                    ldsm4(bL[0],bL[1],bL[2],bL[3],     aWL + (rowB*LTS + kb*32 + colB8)*2);
                    mma_f16(d0, aH0, bH + 0);  mma_f16(d0, aH1, bH + 2);
                    mma_f16(d1, aH0, bL + 0);  mma_f16(d1, aH1, bL + 2);
                    mma_f16(d2, aL0, bH + 0);  mma_f16(d2, aL1, bH + 2);
                }
                {
                    int r0 = mt * 16 + gq;
                    int cc = nt * 8 + tq * 2;
                    gates[r0 * 33 + cc]           = d0[0] + d1[0] + d2[0];
                    gates[r0 * 33 + cc + 1]       = d0[1] + d1[1] + d2[1];
                    gates[(r0 + 8) * 33 + cc]     = d0[2] + d1[2] + d2[2];
                    gates[(r0 + 8) * 33 + cc + 1] = d0[3] + d1[3] + d2[3];
                }
            }
            __syncthreads();

            {
                const int b = lane;
                float gv[4];
#pragma unroll
                for (int g = 0; g < 4; ++g) {
                    float s = gpre[g];
                    if (t > 0) s += gates[b * 33 + g * 8 + w];
                    gv[g] = s;
                }
                float i_ = sigmoidf_(gv[0]);
                float f_ = sigmoidf_(gv[1]);
                float gg = tanhf(gv[2]);
                float o_ = sigmoidf_(gv[3]);
                c_state = f_ * c_state + i_ * gg;
                float h = o_ * tanhf(c_state);
                __half hh, hl;
                split2h(h, hh, hl);
                g_hb_h[t & 1][b * 512 + jh] = hh;
                g_hb_l[t & 1][b * 512 + jh] = hl;
                size_t hsix = (size_t)(t * 32 + b) * H_ + jh;
                g_hs_h[hsix] = hh;
                g_hs_l[hsix] = hl;
            }

            __syncthreads();
            if (tid == 0) st_rel(&g_flags[bx * 32], (unsigned)(t + 1));
        }
    } else {
        // =================== FC worker role ===================
        const int j = bx - LNCTA;            // 0..78
        const int n0 = j * 128;
        float* bias_s = (float*)(dyn + OFF_FBS);
        const uint32_t aFB = sb + OFF_FB;
        const uint32_t aAH = sb + OFF_FAH;
        const uint32_t aAL = sb + OFF_FAL;

        {
            const uint4* fw = (const uint4*)g_fcW_h;
#pragma unroll
            for (int it = 0; it < 32; ++it) {
                int idx = tid + it * 256;
                int r = idx >> 6, q = idx & 63;
                cpa16(aFB + (r * FTS + q * 8) * 2, fw + (size_t)(n0 + r) * 64 + q);
            }
            CP_COMMIT();
        }
        for (int i = tid; i < 128; i += 256) {
            int n = n0 + i;
            bias_s[i] = (n < V_) ? fc_b[n] : 0.f;
        }
        CP_WAIT(0);
        __syncthreads();

        const int rowA  = lane & 15;
        const int colA8 = (lane >> 4) << 3;
        const int g2    = lane >> 3;
        const int rowB  = w * 16 + ((g2 & 2) << 2) + (lane & 7);
        const int colB8 = (g2 & 1) << 3;
        const int gq = lane >> 2, tq = lane & 3;

        for (int t = 0; t < 64; ++t) {
            // ---- dataflow staging: wait on my producer only ----
            wait_flag(srcq, (unsigned)(t + 1));
            {
                const uint4* hh = (const uint4*)(g_hs_h + (size_t)t * 32 * 512);
                const uint4* hl = (const uint4*)(g_hs_l + (size_t)t * 32 * 512);
#pragma unroll
                for (int it = 0; it < 8; ++it) {
                    int idx = tid + it * 256;          // = b*64 + srcq
                    int b = idx >> 6;
                    cpa16(aAH + (b * FTS + srcq * 8) * 2, hh + idx);
                    cpa16(aAL + (b * FTS + srcq * 8) * 2, hl + idx);
                }
                CP_COMMIT();
                CP_WAIT(0);
                __syncthreads();
            }

            float d[2][2][4];
#pragma unroll
            for (int i = 0; i < 2; i++)
#pragma unroll
                for (int jn = 0; jn < 2; jn++)
#pragma unroll
                    for (int q = 0; q < 4; q++) d[i][jn][q] = 0.f;
#pragma unroll
            for (int kb = 0; kb < 32; ++kb) {
                uint32_t aH[2][4], aL[2][4], b[2][2];
                ldsm4(aH[0][0],aH[0][1],aH[0][2],aH[0][3], aAH + ((rowA     )*FTS + kb*16 + colA8)*2);
                ldsm4(aH[1][0],aH[1][1],aH[1][2],aH[1][3], aAH + ((rowA + 16)*FTS + kb*16 + colA8)*2);
                ldsm4(aL[0][0],aL[0][1],aL[0][2],aL[0][3], aAL + ((rowA     )*FTS + kb*16 + colA8)*2);
                ldsm4(aL[1][0],aL[1][1],aL[1][2],aL[1][3], aAL + ((rowA + 16)*FTS + kb*16 + colA8)*2);
                ldsm4(b[0][0], b[0][1], b[1][0], b[1][1],  aFB + (rowB*FTS + kb*16 + colB8)*2);
#pragma unroll
                for (int mb = 0; mb < 2; ++mb)
#pragma unroll
                    for (int nb = 0; nb < 2; ++nb) {
                        mma_f16(d[mb][nb], aH[mb], b[nb]);
                        mma_f16(d[mb][nb], aL[mb], b[nb]);
                    }
            }

#pragma unroll
            for (int mb = 0; mb < 2; ++mb) {
#pragma unroll
                for (int half = 0; half < 2; ++half) {
                    int b = mb * 16 + gq + half * 8;
                    float* crow = out + (size_t)b * (T_ * V_) + (size_t)t * V_;
#pragma unroll
                    for (int nb = 0; nb < 2; ++nb) {
                        int nl = w * 16 + nb * 8 + tq * 2;
                        int n  = n0 + nl;
                        if (n < V_) {
                            float2 o;
                            o.x = d[mb][nb][half * 2 + 0] + bias_s[nl];
                            o.y = d[mb][nb][half * 2 + 1] + bias_s[nl + 1];
                            *(float2*)&crow[n] = o;
                        }
                    }
                }
            }
            __syncthreads();
        }
    }
}

// ------------------------- launch ------------------------------------------
extern "C" void kernel_launch(void* const* d_in, const int* in_sizes, int n_in,
                              void* d_out, int out_size)
{
    const float* features = (const float*)d_in[0];
    const int*   captions = (const int*)d_in[1];
    // d_in[2] = forward_approach (unused)
    const float* embed = (const float*)d_in[3];
    const float* W_ih  = (const float*)d_in[4];
    const float* W_hh  = (const float*)d_in[5];
    const float* b_ih  = (const float*)d_in[6];
    const float* b_hh  = (const float*)d_in[7];
    const float* fc_W  = (const float*)d_in[8];
    const float* fc_b  = (const float*)d_in[9];
    float* out = (float*)d_out;

    float *pGin, *pbias;
    __half *pXh, *pXl, *pWih_h, *pWih_l, *pWhh_h, *pWhh_l, *pfcW_h;
    cudaGetSymbolAddress((void**)&pGin,   g_Gin);
    cudaGetSymbolAddress((void**)&pbias,  g_biasg);
    cudaGetSymbolAddress((void**)&pXh,    g_Xh);
    cudaGetSymbolAddress((void**)&pXl,    g_Xl);
    cudaGetSymbolAddress((void**)&pWih_h, g_Wih_h);
    cudaGetSymbolAddress((void**)&pWih_l, g_Wih_l);
    cudaGetSymbolAddress((void**)&pWhh_h, g_Whh_h);
    cudaGetSymbolAddress((void**)&pWhh_l, g_Whh_l);
    cudaGetSymbolAddress((void**)&pfcW_h, g_fcW_h);

    const int SMEM_G3 = 2 * 4 * TILE_B + 512;
    cudaFuncSetAttribute(gin_gemm, cudaFuncAttributeMaxDynamicSharedMemorySize, SMEM_G3);
    cudaFuncSetAttribute(fused_lstm_fc, cudaFuncAttributeMaxDynamicSharedMemorySize, FUSED_SMEM);

    // 1) build split X + fused bias + reset barrier flags
    prep_kernel<<<(T_ * B_ * E_ / 4) / 256, 256>>>(
        (const float4*)features, captions, (const float4*)embed,
        (const float4*)b_ih, (const float4*)b_hh);

    // 2) split weights (vectorized; fc_W hi-only)
    split_kernel<true ><<<(G_ * E_ / 4 + 255) / 256, 256>>>(
        (const float4*)W_ih, (uint2*)pWih_h, (uint2*)pWih_l, G_ * E_ / 4, G_ * E_ / 4);
    split_kernel<true ><<<(G_ * H_ / 4 + 255) / 256, 256>>>(
        (const float4*)W_hh, (uint2*)pWhh_h, (uint2*)pWhh_l, G_ * H_ / 4, G_ * H_ / 4);
    split_kernel<false><<<(VPAD * H_ / 4 + 255) / 256, 256>>>(
        (const float4*)fc_W, (uint2*)pfcW_h, nullptr, V_ * H_ / 4, VPAD * H_ / 4);

    // 3) Gin[t][n][b] = X @ W_ih^T + (b_ih + b_hh)   (fp16 3-pass)
    gin_gemm<<<dim3(G_ / 128, (T_ * B_) / 128), 256, SMEM_G3>>>(
        pXh, pXl, pWih_h, pWih_l, pbias, pGin);

    // 4) fused persistent LSTM + FC (143 CTAs, dataflow sync)
    fused_lstm_fc<<<LNCTA + FNCTA, 256, FUSED_SMEM>>>(fc_b, out);
}

// round 10
// speedup vs baseline: 3.1786x; 1.3255x over previous
#include <cuda_runtime.h>
#include <cuda_fp16.h>
#include <math.h>
#include <stdint.h>

#define B_  32
#define T_  64
#define E_  512
#define H_  512
#define V_  10000
#define G_  2048          // 4*H
#define VPAD 10112        // 79 * 128
#define LNCTA 64          // LSTM CTAs
#define FNCTA 79          // FC worker CTAs

// ------------------------- device scratch (no allocs allowed) ---------------
__device__ __half g_Xh  [T_ * B_ * E_];
__device__ __half g_Xl  [T_ * B_ * E_];
__device__ __half g_Wih_h[G_ * E_];
__device__ __half g_Wih_l[G_ * E_];
__device__ __half g_Whh_h[G_ * H_];
__device__ __half g_Whh_l[G_ * H_];
__device__ __half g_fcW_h[VPAD * H_];
__device__ __half g_hsb [T_ * B_ * H_];   // h history, fp16, b-major per t
__device__ float g_Gin [T_ * G_ * B_];    // [t][n][b]
__device__ float g_biasg[G_];
__device__ unsigned g_flags[LNCTA * 32];  // 128B-strided per-CTA step flags

// ------------------------- helpers (baseline PTX, sm_80+) -------------------
__device__ __forceinline__ uint32_t smem_u32(const void* p) {
    uint32_t a;
    asm("{ .reg .u64 t; cvta.to.shared.u64 t, %1; cvt.u32.u64 %0, t; }"
        : "=r"(a) : "l"(p));
    return a;
}
__device__ __forceinline__ void ldsm4(uint32_t& r0, uint32_t& r1,
                                      uint32_t& r2, uint32_t& r3, uint32_t addr) {
    asm volatile("ldmatrix.sync.aligned.m8n8.x4.shared.b16 {%0,%1,%2,%3}, [%4];"
                 : "=r"(r0), "=r"(r1), "=r"(r2), "=r"(r3) : "r"(addr));
}
__device__ __forceinline__ void mma_f16(float* d, const uint32_t* a, const uint32_t* b) {
    asm volatile(
        "mma.sync.aligned.m16n8k16.row.col.f32.f16.f16.f32 "
        "{%0,%1,%2,%3}, {%4,%5,%6,%7}, {%8,%9}, {%0,%1,%2,%3};"
        : "+f"(d[0]), "+f"(d[1]), "+f"(d[2]), "+f"(d[3])
        : "r"(a[0]), "r"(a[1]), "r"(a[2]), "r"(a[3]), "r"(b[0]), "r"(b[1]));
}
__device__ __forceinline__ void cpa16(uint32_t saddr, const void* g) {
    asm volatile("cp.async.cg.shared.global [%0], [%1], 16;" :: "r"(saddr), "l"(g));
}
#define CP_COMMIT() asm volatile("cp.async.commit_group;" ::: "memory")
#define CP_WAIT(n)  asm volatile("cp.async.wait_group %0;" :: "n"(n) : "memory")

__device__ __forceinline__ unsigned ld_acq(const unsigned* p) {
    unsigned v;
    asm volatile("ld.acquire.gpu.u32 %0, [%1];" : "=r"(v) : "l"(p) : "memory");
    return v;
}
__device__ __forceinline__ void st_rel(unsigned* p, unsigned v) {
    asm volatile("st.release.gpu.u32 [%0], %1;" :: "l"(p), "r"(v) : "memory");
}
__device__ __forceinline__ void wait_flag(int q, unsigned target) {
    while (ld_acq(&g_flags[q * 32]) < target) { __nanosleep(16); }
}
__device__ __forceinline__ uint32_t h2u(__half2 h) {
    return *reinterpret_cast<uint32_t*>(&h);
}
__device__ __forceinline__ float sigmoidf_(float x) { return 1.f / (1.f + expf(-x)); }

// ------------------------- prep: split-X (vectorized) + bias + flag reset ---
__global__ void prep_kernel(const float4* __restrict__ features4,
                            const int* __restrict__ captions,
                            const float4* __restrict__ embed4,
                            const float4* __restrict__ b_ih4,
                            const float4* __restrict__ b_hh4)
{
    int i = blockIdx.x * blockDim.x + threadIdx.x;   // over T*B*E/4 = 262,144
    int e4 = i & 127;
    int b  = (i >> 7) & (B_ - 1);
    int t  = i >> 12;
    float4 v;
    if (t == 0) {
        v = features4[b * 128 + e4];
    } else {
        int tok = captions[b * T_ + (t - 1)];
        tok = min(max(tok, 0), V_ - 1);
        v = embed4[(size_t)tok * 128 + e4];
    }
    __half2 h0 = __floats2half2_rn(v.x, v.y);
    __half2 h1 = __floats2half2_rn(v.z, v.w);
    float2 r0 = __half22float2(h0), r1 = __half22float2(h1);
    __half2 l0 = __floats2half2_rn(v.x - r0.x, v.y - r0.y);
    __half2 l1 = __floats2half2_rn(v.z - r1.x, v.w - r1.y);
    ((uint2*)g_Xh)[i] = make_uint2(h2u(h0), h2u(h1));
    ((uint2*)g_Xl)[i] = make_uint2(h2u(l0), h2u(l1));
    if (i < G_ / 4) {
        float4 a = b_ih4[i], c = b_hh4[i];
        ((float4*)g_biasg)[i] = make_float4(a.x + c.x, a.y + c.y, a.z + c.z, a.w + c.w);
    }
    if (i < LNCTA * 32) g_flags[i] = 0;
}

// ------------------------- weight split (vectorized, lo optional) -----------
template<bool LO>
__global__ void split_kernel(const float4* __restrict__ src,
                             uint2* __restrict__ hi, uint2* __restrict__ lo,
                             int n4_valid, int n4_pad)
{
    int i = blockIdx.x * 256 + threadIdx.x;
    if (i >= n4_pad) return;
    float4 v = (i < n4_valid) ? src[i] : make_float4(0.f, 0.f, 0.f, 0.f);
    __half2 h0 = __floats2half2_rn(v.x, v.y);
    __half2 h1 = __floats2half2_rn(v.z, v.w);
    hi[i] = make_uint2(h2u(h0), h2u(h1));
    if (LO) {
        float2 r0 = __half22float2(h0), r1 = __half22float2(h1);
        __half2 l0 = __floats2half2_rn(v.x - r0.x, v.y - r0.y);
        __half2 l1 = __floats2half2_rn(v.z - r1.x, v.w - r1.y);
        lo[i] = make_uint2(h2u(l0), h2u(l1));
    }
}

// ------------------------- Gin GEMM (fp16 3-pass, cp.async pipelined) -------
#define TS 40
#define TILE_B (128 * TS * 2)

__global__ void __launch_bounds__(256, 2)
gin_gemm(const __half* __restrict__ Ah, const __half* __restrict__ Al,
         const __half* __restrict__ Bh, const __half* __restrict__ Bl,
         const float* __restrict__ bias, float* __restrict__ C)
{
    constexpr int NT = 4;
    constexpr int STAGE = NT * TILE_B;

    extern __shared__ uint8_t dyn[];
    float* bias_s = (float*)(dyn + 2 * STAGE);

    const int tid  = threadIdx.x;
    const int wid  = tid >> 5;
    const int lane = tid & 31;
    const int n0   = blockIdx.x * 128;
    const int m0   = blockIdx.y * 128;

    const int mbase = (wid >> 1) * 32;
    const int nbase = (wid & 1) * 64;

    for (int i = tid; i < 128; i += 256) bias_s[i] = bias[n0 + i];

    const int rowA  = mbase + (lane & 15);
    const int colA8 = (lane >> 4) << 3;
    const int g2    = lane >> 3;
    const int rowB  = nbase + ((g2 & 2) << 2) + (lane & 7);
    const int colB8 = (g2 & 1) << 3;

    const uint32_t sbase = smem_u32(dyn);

    const uint4* gsrc[4] = {
        (const uint4*)(Ah + (size_t)m0 * 512), (const uint4*)(Al + (size_t)m0 * 512),
        (const uint4*)(Bh + (size_t)n0 * 512), (const uint4*)(Bl + (size_t)n0 * 512) };

    float d[2][8][4];
#pragma unroll
    for (int i = 0; i < 2; i++)
#pragma unroll
        for (int j = 0; j < 8; j++)
#pragma unroll
            for (int q = 0; q < 4; q++) d[i][j][q] = 0.f;

#pragma unroll
    for (int it = 0; it < 8; ++it) {
        int s = tid + it * 256, mat = s >> 9, rem = s & 511, row = rem >> 2, q = rem & 3;
        cpa16(sbase + mat * TILE_B + (row * TS + q * 8) * 2,
              gsrc[mat] + (size_t)row * 64 + q);
    }
    CP_COMMIT();

    for (int kc = 0; kc < 16; ++kc) {
        const int cur = kc & 1;
        if (kc < 15) {
            const uint32_t st = sbase + (cur ^ 1) * STAGE;
#pragma unroll
            for (int it = 0; it < 8; ++it) {
                int s = tid + it * 256, mat = s >> 9, rem = s & 511, row = rem >> 2, q = rem & 3;
                cpa16(st + mat * TILE_B + (row * TS + q * 8) * 2,
                      gsrc[mat] + (size_t)row * 64 + (kc + 1) * 4 + q);
            }
            CP_COMMIT();
            CP_WAIT(1);
        } else {
            CP_WAIT(0);
        }
        __syncthreads();

        const uint32_t aAh = sbase + cur * STAGE;
        const uint32_t aAl = aAh + TILE_B;
        const uint32_t aBh = aAl + TILE_B;
        const uint32_t aBl = aBh + TILE_B;
#pragma unroll
        for (int ks = 0; ks < 2; ++ks) {
#pragma unroll
            for (int p = 0; p < 3; ++p) {
                const uint32_t baseA = (p == 2) ? aAl : aAh;
                const uint32_t baseB = (p == 1) ? aBl : aBh;
                uint32_t a[2][4], b[8][2];
#pragma unroll
                for (int mb = 0; mb < 2; ++mb)
                    ldsm4(a[mb][0], a[mb][1], a[mb][2], a[mb][3],
                          baseA + ((rowA + mb * 16) * TS + ks * 16 + colA8) * 2);
#pragma unroll
                for (int nbp = 0; nbp < 4; ++nbp)
                    ldsm4(b[2*nbp][0], b[2*nbp][1], b[2*nbp+1][0], b[2*nbp+1][1],
                          baseB + ((rowB + nbp * 16) * TS + ks * 16 + colB8) * 2);
#pragma unroll
                for (int mb = 0; mb < 2; ++mb)
#pragma unroll
                    for (int nb = 0; nb < 8; ++nb)
                        mma_f16(d[mb][nb], a[mb], b[nb]);
            }
        }
        __syncthreads();
    }

    const int gq = lane >> 2, tq = lane & 3;
#pragma unroll
    for (int mb = 0; mb < 2; ++mb) {
#pragma unroll
        for (int half = 0; half < 2; ++half) {
            int m = m0 + mbase + mb * 16 + gq + half * 8;
#pragma unroll
            for (int nb = 0; nb < 8; ++nb) {
                int nl = nbase + nb * 8 + tq * 2;
                int n  = n0 + nl;
                size_t base = (size_t)(m >> 5) * (G_ * B_) + (m & 31);
                C[base + (size_t)n * B_]       = d[mb][nb][half * 2 + 0] + bias_s[nl];
                C[base + (size_t)(n + 1) * B_] = d[mb][nb][half * 2 + 1] + bias_s[nl + 1];
            }
        }
    }
}

// ------------------------- fused persistent LSTM + FC -----------------------
// Grid = 143 CTAs x 256 threads, all co-resident.
//  CTAs [0,64):    LSTM; h stored fp16 (single array g_hsb[t]); gates via
//                  2-pass mma (h*W_hi + h*W_lo).
//  CTAs [64,143):  FC worker j owns out cols [j*128,+128); 1-pass mma.
// Dataflow sync: thread's uint4 slice (srcq = tid & 63) comes from exactly
// one producer CTA; wait only on flag[srcq] with nanosleep backoff.
#define LTS 520
#define L_WROW (32 * LTS * 2)               // 33280
#define OFF_WH 0
#define OFF_WL (OFF_WH + L_WROW)
#define OFF_AH (OFF_WL + L_WROW)
#define OFF_GT (OFF_AH + L_WROW)
#define LSMEM  (OFF_GT + 32 * 33 * 4)       // 104064
// FC layout
#define FTS 520
#define OFF_FB   0
#define FB_BYTES (128 * FTS * 2)            // 133120
#define OFF_FAH  (OFF_FB + FB_BYTES)
#define OFF_FBS  (OFF_FAH + 32 * FTS * 2)   // 166400
#define FSMEM    (OFF_FBS + 512)            // 166912
#define FUSED_SMEM (FSMEM > LSMEM ? FSMEM : LSMEM)

__global__ void __launch_bounds__(256, 1)
fused_lstm_fc(const float* __restrict__ fc_b, float* __restrict__ out)
{
    extern __shared__ uint8_t dyn[];
    const int tid  = threadIdx.x;
    const int bx   = blockIdx.x;
    const int w    = tid >> 5;
    const int lane = tid & 31;
    const uint32_t sb = smem_u32(dyn);
    const int srcq = tid & 63;

    if (bx < LNCTA) {
        // =================== LSTM role ===================
        float* gates = (float*)(dyn + OFF_GT);
        const uint32_t aWH = sb + OFF_WH;
        const uint32_t aWL = sb + OFF_WL;
        const uint32_t aAH = sb + OFF_AH;

        {
            const uint4* wh = (const uint4*)g_Whh_h;
            const uint4* wl = (const uint4*)g_Whh_l;
#pragma unroll
            for (int it = 0; it < 8; ++it) {
                int idx = tid + it * 256;
                int r = idx >> 6, q = idx & 63;
                int gr = (r >> 3) * 512 + bx * 8 + (r & 7);
                cpa16(aWH + (r * LTS + q * 8) * 2, wh + (size_t)gr * 64 + q);
                cpa16(aWL + (r * LTS + q * 8) * 2, wl + (size_t)gr * 64 + q);
            }
            CP_COMMIT();
            CP_WAIT(0);
        }

        const int mt = w & 1;
        const int nt = w >> 1;
        const int rowA  = mt * 16 + (lane & 15);
        const int colA8 = (lane >> 4) << 3;
        const int rowB  = nt * 8 + (lane & 7);
        const int colB8 = (lane >> 3) << 3;
        const int gq = lane >> 2, tq = lane & 3;

        float c_state = 0.f;
        const int jh = bx * 8 + w;
        __syncthreads();

        for (int t = 0; t < 64; ++t) {
            float gpre[4];
#pragma unroll
            for (int g = 0; g < 4; ++g)
                gpre[g] = __ldcg(&g_Gin[(size_t)t * (G_ * B_)
                                        + (size_t)(g * 512 + jh) * B_ + lane]);

            if (t > 0) {
                // ---- dataflow staging: wait on my producer, stage its slice ----
                wait_flag(srcq, (unsigned)t);
                const uint4* hh = (const uint4*)(g_hsb + (size_t)(t - 1) * B_ * H_);
#pragma unroll
                for (int it = 0; it < 8; ++it) {
                    int idx = tid + it * 256;          // = b*64 + srcq
                    int b = idx >> 6;
                    cpa16(aAH + (b * LTS + srcq * 8) * 2, hh + idx);
                }
                CP_COMMIT();
                CP_WAIT(0);
                __syncthreads();

                // ---- gates = h @ [W_hi; W_lo]^T : 2 chains x 32 k-steps ----
                float d0[4] = {0,0,0,0}, d1[4] = {0,0,0,0};
#pragma unroll
                for (int kb = 0; kb < 16; ++kb) {
                    uint32_t aH0[4], aH1[4], bH[4], bL[4];
                    ldsm4(aH0[0],aH0[1],aH0[2],aH0[3], aAH + (rowA*LTS + kb*32      + colA8)*2);
                    ldsm4(aH1[0],aH1[1],aH1[2],aH1[3], aAH + (rowA*LTS + kb*32 + 16 + colA8)*2);
                    ldsm4(bH[0],bH[1],bH[2],bH[3],     aWH + (rowB*LTS + kb*32 + colB8)*2);
                    ldsm4(bL[0],bL[1],bL[2],bL[3],     aWL + (rowB*LTS + kb*32 + colB8)*2);
                    mma_f16(d0, aH0, bH + 0);  mma_f16(d0, aH1, bH + 2);
                    mma_f16(d1, aH0, bL + 0);  mma_f16(d1, aH1, bL + 2);
                }
                {
                    int r0 = mt * 16 + gq;
                    int cc = nt * 8 + tq * 2;
                    gates[r0 * 33 + cc]           = d0[0] + d1[0];
                    gates[r0 * 33 + cc + 1]       = d0[1] + d1[1];
                    gates[(r0 + 8) * 33 + cc]     = d0[2] + d1[2];
                    gates[(r0 + 8) * 33 + cc + 1] = d0[3] + d1[3];
                }
            }
            __syncthreads();

            {
                const int b = lane;
                float gv[4];
#pragma unroll
                for (int g = 0; g < 4; ++g) {
                    float s = gpre[g];
                    if (t > 0) s += gates[b * 33 + g * 8 + w];
                    gv[g] = s;
                }
                float i_ = sigmoidf_(gv[0]);
                float f_ = sigmoidf_(gv[1]);
                float gg = tanhf(gv[2]);
                float o_ = sigmoidf_(gv[3]);
                c_state = f_ * c_state + i_ * gg;
                float h = o_ * tanhf(c_state);
                g_hsb[(size_t)t * B_ * H_ + b * 512 + jh] = __float2half(h);
            }

            __syncthreads();
            if (tid == 0) st_rel(&g_flags[bx * 32], (unsigned)(t + 1));
        }
    } else {
        // =================== FC worker role ===================
        const int j = bx - LNCTA;            // 0..78
        const int n0 = j * 128;
        float* bias_s = (float*)(dyn + OFF_FBS);
        const uint32_t aFB = sb + OFF_FB;
        const uint32_t aAH = sb + OFF_FAH;

        {
            const uint4* fw = (const uint4*)g_fcW_h;
#pragma unroll
            for (int it = 0; it < 32; ++it) {
                int idx = tid + it * 256;
                int r = idx >> 6, q = idx & 63;
                cpa16(aFB + (r * FTS + q * 8) * 2, fw + (size_t)(n0 + r) * 64 + q);
            }
            CP_COMMIT();
        }
        for (int i = tid; i < 128; i += 256) {
            int n = n0 + i;
            bias_s[i] = (n < V_) ? fc_b[n] : 0.f;
        }
        CP_WAIT(0);
        __syncthreads();

        const int rowA  = lane & 15;
        const int colA8 = (lane >> 4) << 3;
        const int g2    = lane >> 3;
        const int rowB  = w * 16 + ((g2 & 2) << 2) + (lane & 7);
        const int colB8 = (g2 & 1) << 3;
        const int gq = lane >> 2, tq = lane & 3;

        for (int t = 0; t < 64; ++t) {
            wait_flag(srcq, (unsigned)(t + 1));
            {
                const uint4* hh = (const uint4*)(g_hsb + (size_t)t * B_ * H_);
#pragma unroll
                for (int it = 0; it < 8; ++it) {
                    int idx = tid + it * 256;          // = b*64 + srcq
                    int b = idx >> 6;
                    cpa16(aAH + (b * FTS + srcq * 8) * 2, hh + idx);
                }
                CP_COMMIT();
                CP_WAIT(0);
                __syncthreads();
            }

            // 1-pass mma: out32x16 = h @ Btile^T
            float d[2][2][4];
#pragma unroll
            for (int i = 0; i < 2; i++)
#pragma unroll
                for (int jn = 0; jn < 2; jn++)
#pragma unroll
                    for (int q = 0; q < 4; q++) d[i][jn][q] = 0.f;
#pragma unroll
            for (int kb = 0; kb < 32; ++kb) {
                uint32_t aH[2][4], b[2][2];
                ldsm4(aH[0][0],aH[0][1],aH[0][2],aH[0][3], aAH + ((rowA     )*FTS + kb*16 + colA8)*2);
                ldsm4(aH[1][0],aH[1][1],aH[1][2],aH[1][3], aAH + ((rowA + 16)*FTS + kb*16 + colA8)*2);
                ldsm4(b[0][0], b[0][1], b[1][0], b[1][1],  aFB + (rowB*FTS + kb*16 + colB8)*2);
#pragma unroll
                for (int mb = 0; mb < 2; ++mb)
#pragma unroll
                    for (int nb = 0; nb < 2; ++nb)
                        mma_f16(d[mb][nb], aH[mb], b[nb]);
            }

#pragma unroll
            for (int mb = 0; mb < 2; ++mb) {
#pragma unroll
                for (int half = 0; half < 2; ++half) {
                    int b = mb * 16 + gq + half * 8;
                    float* crow = out + (size_t)b * (T_ * V_) + (size_t)t * V_;
#pragma unroll
                    for (int nb = 0; nb < 2; ++nb) {
                        int nl = w * 16 + nb * 8 + tq * 2;
                        int n  = n0 + nl;
                        if (n < V_) {
                            float2 o;
                            o.x = d[mb][nb][half * 2 + 0] + bias_s[nl];
                            o.y = d[mb][nb][half * 2 + 1] + bias_s[nl + 1];
                            *(float2*)&crow[n] = o;
                        }
                    }
                }
            }
            __syncthreads();
        }
    }
}

// ------------------------- launch ------------------------------------------
extern "C" void kernel_launch(void* const* d_in, const int* in_sizes, int n_in,
                              void* d_out, int out_size)
{
    const float* features = (const float*)d_in[0];
    const int*   captions = (const int*)d_in[1];
    // d_in[2] = forward_approach (unused)
    const float* embed = (const float*)d_in[3];
    const float* W_ih  = (const float*)d_in[4];
    const float* W_hh  = (const float*)d_in[5];
    const float* b_ih  = (const float*)d_in[6];
    const float* b_hh  = (const float*)d_in[7];
    const float* fc_W  = (const float*)d_in[8];
    const float* fc_b  = (const float*)d_in[9];
    float* out = (float*)d_out;

    float *pGin, *pbias;
    __half *pXh, *pXl, *pWih_h, *pWih_l, *pWhh_h, *pWhh_l, *pfcW_h;
    cudaGetSymbolAddress((void**)&pGin,   g_Gin);
    cudaGetSymbolAddress((void**)&pbias,  g_biasg);
    cudaGetSymbolAddress((void**)&pXh,    g_Xh);
    cudaGetSymbolAddress((void**)&pXl,    g_Xl);
    cudaGetSymbolAddress((void**)&pWih_h, g_Wih_h);
    cudaGetSymbolAddress((void**)&pWih_l, g_Wih_l);
    cudaGetSymbolAddress((void**)&pWhh_h, g_Whh_h);
    cudaGetSymbolAddress((void**)&pWhh_l, g_Whh_l);
    cudaGetSymbolAddress((void**)&pfcW_h, g_fcW_h);

    const int SMEM_G3 = 2 * 4 * TILE_B + 512;
    cudaFuncSetAttribute(gin_gemm, cudaFuncAttributeMaxDynamicSharedMemorySize, SMEM_G3);
    cudaFuncSetAttribute(fused_lstm_fc, cudaFuncAttributeMaxDynamicSharedMemorySize, FUSED_SMEM);

    // 1) build split X + fused bias + reset barrier flags
    prep_kernel<<<(T_ * B_ * E_ / 4) / 256, 256>>>(
        (const float4*)features, captions, (const float4*)embed,
        (const float4*)b_ih, (const float4*)b_hh);

    // 2) split weights (vectorized; fc_W hi-only)
    split_kernel<true ><<<(G_ * E_ / 4 + 255) / 256, 256>>>(
        (const float4*)W_ih, (uint2*)pWih_h, (uint2*)pWih_l, G_ * E_ / 4, G_ * E_ / 4);
    split_kernel<true ><<<(G_ * H_ / 4 + 255) / 256, 256>>>(
        (const float4*)W_hh, (uint2*)pWhh_h, (uint2*)pWhh_l, G_ * H_ / 4, G_ * H_ / 4);
    split_kernel<false><<<(VPAD * H_ / 4 + 255) / 256, 256>>>(
        (const float4*)fc_W, (uint2*)pfcW_h, nullptr, V_ * H_ / 4, VPAD * H_ / 4);

    // 3) Gin[t][n][b] = X @ W_ih^T + (b_ih + b_hh)   (fp16 3-pass)
    gin_gemm<<<dim3(G_ / 128, (T_ * B_) / 128), 256, SMEM_G3>>>(
        pXh, pXl, pWih_h, pWih_l, pbias, pGin);

    // 4) fused persistent LSTM + FC (fp16 h, 2-pass gates, 1-pass FC)
    fused_lstm_fc<<<LNCTA + FNCTA, 256, FUSED_SMEM>>>(fc_b, out);
}

// round 11
// speedup vs baseline: 3.6480x; 1.1477x over previous
#include <cuda_runtime.h>
#include <cuda_fp16.h>
#include <math.h>
#include <stdint.h>

#define B_  32
#define T_  64
#define E_  512
#define H_  512
#define V_  10000
#define G_  2048          // 4*H
#define LNCTA 64          // LSTM CTAs
#define FNCTA 79          // FC worker CTAs

// ------------------------- device scratch (no allocs allowed) ---------------
__device__ __half g_Xh  [T_ * B_ * E_];
__device__ __half g_Xl  [T_ * B_ * E_];
__device__ __half g_Wih_h[G_ * E_];
__device__ __half g_hsb [T_ * B_ * H_];   // h history, fp16, b-major per t
__device__ float g_Gin [T_ * G_ * B_];    // [t][n][b]
__device__ float g_biasg[G_];
__device__ unsigned g_flags[LNCTA * 32];  // 128B-strided per-CTA step flags

// ------------------------- helpers (baseline PTX, sm_80+) -------------------
__device__ __forceinline__ uint32_t smem_u32(const void* p) {
    uint32_t a;
    asm("{ .reg .u64 t; cvta.to.shared.u64 t, %1; cvt.u32.u64 %0, t; }"
        : "=r"(a) : "l"(p));
    return a;
}
__device__ __forceinline__ void ldsm4(uint32_t& r0, uint32_t& r1,
                                      uint32_t& r2, uint32_t& r3, uint32_t addr) {
    asm volatile("ldmatrix.sync.aligned.m8n8.x4.shared.b16 {%0,%1,%2,%3}, [%4];"
                 : "=r"(r0), "=r"(r1), "=r"(r2), "=r"(r3) : "r"(addr));
}
__device__ __forceinline__ void mma_f16(float* d, const uint32_t* a, const uint32_t* b) {
    asm volatile(
        "mma.sync.aligned.m16n8k16.row.col.f32.f16.f16.f32 "
        "{%0,%1,%2,%3}, {%4,%5,%6,%7}, {%8,%9}, {%0,%1,%2,%3};"
        : "+f"(d[0]), "+f"(d[1]), "+f"(d[2]), "+f"(d[3])
        : "r"(a[0]), "r"(a[1]), "r"(a[2]), "r"(a[3]), "r"(b[0]), "r"(b[1]));
}
__device__ __forceinline__ void cpa16(uint32_t saddr, const void* g) {
    asm volatile("cp.async.cg.shared.global [%0], [%1], 16;" :: "r"(saddr), "l"(g));
}
#define CP_COMMIT() asm volatile("cp.async.commit_group;" ::: "memory")
#define CP_WAIT(n)  asm volatile("cp.async.wait_group %0;" :: "n"(n) : "memory")

__device__ __forceinline__ unsigned ld_acq(const unsigned* p) {
    unsigned v;
    asm volatile("ld.acquire.gpu.u32 %0, [%1];" : "=r"(v) : "l"(p) : "memory");
    return v;
}
__device__ __forceinline__ void st_rel(unsigned* p, unsigned v) {
    asm volatile("st.release.gpu.u32 [%0], %1;" :: "l"(p), "r"(v) : "memory");
}
__device__ __forceinline__ void wait_flag(int q, unsigned target) {
    while (ld_acq(&g_flags[q * 32]) < target) { __nanosleep(16); }
}
__device__ __forceinline__ uint32_t h2u(__half2 h) {
    return *reinterpret_cast<uint32_t*>(&h);
}
__device__ __forceinline__ float sigmoidf_(float x) { return 1.f / (1.f + expf(-x)); }

// split one float4 into hi/lo half2-pairs
__device__ __forceinline__ void split4(float4 v, uint2& hi, uint2& lo) {
    __half2 h0 = __floats2half2_rn(v.x, v.y);
    __half2 h1 = __floats2half2_rn(v.z, v.w);
    float2 r0 = __half22float2(h0), r1 = __half22float2(h1);
    __half2 l0 = __floats2half2_rn(v.x - r0.x, v.y - r0.y);
    __half2 l1 = __floats2half2_rn(v.z - r1.x, v.w - r1.y);
    hi = make_uint2(h2u(h0), h2u(h1));
    lo = make_uint2(h2u(l0), h2u(l1));
}

// ------------------------- prep: split-X (vectorized) + bias + flag reset ---
__global__ void prep_kernel(const float4* __restrict__ features4,
                            const int* __restrict__ captions,
                            const float4* __restrict__ embed4,
                            const float4* __restrict__ b_ih4,
                            const float4* __restrict__ b_hh4)
{
    int i = blockIdx.x * blockDim.x + threadIdx.x;   // over T*B*E/4 = 262,144
    int e4 = i & 127;
    int b  = (i >> 7) & (B_ - 1);
    int t  = i >> 12;
    float4 v;
    if (t == 0) {
        v = features4[b * 128 + e4];
    } else {
        int tok = captions[b * T_ + (t - 1)];
        tok = min(max(tok, 0), V_ - 1);
        v = embed4[(size_t)tok * 128 + e4];
    }
    uint2 hi, lo;
    split4(v, hi, lo);
    ((uint2*)g_Xh)[i] = hi;
    ((uint2*)g_Xl)[i] = lo;
    if (i < G_ / 4) {
        float4 a = b_ih4[i], c = b_hh4[i];
        ((float4*)g_biasg)[i] = make_float4(a.x + c.x, a.y + c.y, a.z + c.z, a.w + c.w);
    }
    if (i < LNCTA * 32) g_flags[i] = 0;
}

// ------------------------- W_ih hi-only split --------------------------------
__global__ void split_hi_kernel(const float4* __restrict__ src,
                                uint2* __restrict__ hi, int n4)
{
    int i = blockIdx.x * 256 + threadIdx.x;
    if (i >= n4) return;
    float4 v = src[i];
    __half2 h0 = __floats2half2_rn(v.x, v.y);
    __half2 h1 = __floats2half2_rn(v.z, v.w);
    hi[i] = make_uint2(h2u(h0), h2u(h1));
}

// ------------------------- Gin GEMM (fp16 2-pass, cp.async pipelined) -------
// Gin = (Xh + Xl) @ Wih_h^T + bias   (X split hi/lo, W fp16-rounded)
#define TS 40
#define TILE_B (128 * TS * 2)

__global__ void __launch_bounds__(256, 2)
gin_gemm(const __half* __restrict__ Ah, const __half* __restrict__ Al,
         const __half* __restrict__ Bh,
         const float* __restrict__ bias, float* __restrict__ C)
{
    constexpr int NT = 3;
    constexpr int STAGE = NT * TILE_B;

    extern __shared__ uint8_t dyn[];
    float* bias_s = (float*)(dyn + 2 * STAGE);

    const int tid  = threadIdx.x;
    const int wid  = tid >> 5;
    const int lane = tid & 31;
    const int n0   = blockIdx.x * 128;
    const int m0   = blockIdx.y * 128;

    const int mbase = (wid >> 1) * 32;
    const int nbase = (wid & 1) * 64;

    for (int i = tid; i < 128; i += 256) bias_s[i] = bias[n0 + i];

    const int rowA  = mbase + (lane & 15);
    const int colA8 = (lane >> 4) << 3;
    const int g2    = lane >> 3;
    const int rowB  = nbase + ((g2 & 2) << 2) + (lane & 7);
    const int colB8 = (g2 & 1) << 3;

    const uint32_t sbase = smem_u32(dyn);

    const uint4* gsrc[3] = {
        (const uint4*)(Ah + (size_t)m0 * 512), (const uint4*)(Al + (size_t)m0 * 512),
        (const uint4*)(Bh + (size_t)n0 * 512) };

    float d[2][8][4];
#pragma unroll
    for (int i = 0; i < 2; i++)
#pragma unroll
        for (int j = 0; j < 8; j++)
#pragma unroll
            for (int q = 0; q < 4; q++) d[i][j][q] = 0.f;

#pragma unroll
    for (int it = 0; it < 6; ++it) {
        int s = tid + it * 256, mat = s >> 9, rem = s & 511, row = rem >> 2, q = rem & 3;
        cpa16(sbase + mat * TILE_B + (row * TS + q * 8) * 2,
              gsrc[mat] + (size_t)row * 64 + q);
    }
    CP_COMMIT();

    for (int kc = 0; kc < 16; ++kc) {
        const int cur = kc & 1;
        if (kc < 15) {
            const uint32_t st = sbase + (cur ^ 1) * STAGE;
#pragma unroll
            for (int it = 0; it < 6; ++it) {
                int s = tid + it * 256, mat = s >> 9, rem = s & 511, row = rem >> 2, q = rem & 3;
                cpa16(st + mat * TILE_B + (row * TS + q * 8) * 2,
                      gsrc[mat] + (size_t)row * 64 + (kc + 1) * 4 + q);
            }
            CP_COMMIT();
            CP_WAIT(1);
        } else {
            CP_WAIT(0);
        }
        __syncthreads();

        const uint32_t aAh = sbase + cur * STAGE;
        const uint32_t aAl = aAh + TILE_B;
        const uint32_t aBh = aAl + TILE_B;
#pragma unroll
        for (int ks = 0; ks < 2; ++ks) {
#pragma unroll
            for (int p = 0; p < 2; ++p) {
                const uint32_t baseA = p ? aAl : aAh;
                uint32_t a[2][4], b[8][2];
#pragma unroll
                for (int mb = 0; mb < 2; ++mb)
                    ldsm4(a[mb][0], a[mb][1], a[mb][2], a[mb][3],
                          baseA + ((rowA + mb * 16) * TS + ks * 16 + colA8) * 2);
#pragma unroll
                for (int nbp = 0; nbp < 4; ++nbp)
                    ldsm4(b[2*nbp][0], b[2*nbp][1], b[2*nbp+1][0], b[2*nbp+1][1],
                          aBh + ((rowB + nbp * 16) * TS + ks * 16 + colB8) * 2);
#pragma unroll
                for (int mb = 0; mb < 2; ++mb)
#pragma unroll
                    for (int nb = 0; nb < 8; ++nb)
                        mma_f16(d[mb][nb], a[mb], b[nb]);
            }
        }
        __syncthreads();
    }

    const int gq = lane >> 2, tq = lane & 3;
#pragma unroll
    for (int mb = 0; mb < 2; ++mb) {
#pragma unroll
        for (int half = 0; half < 2; ++half) {
            int m = m0 + mbase + mb * 16 + gq + half * 8;
#pragma unroll
            for (int nb = 0; nb < 8; ++nb) {
                int nl = nbase + nb * 8 + tq * 2;
                int n  = n0 + nl;
                size_t base = (size_t)(m >> 5) * (G_ * B_) + (m & 31);
                C[base + (size_t)n * B_]       = d[mb][nb][half * 2 + 0] + bias_s[nl];
                C[base + (size_t)(n + 1) * B_] = d[mb][nb][half * 2 + 1] + bias_s[nl + 1];
            }
        }
    }
}

// ------------------------- fused persistent LSTM + FC -----------------------
// Grid = 143 CTAs x 256 threads, all co-resident.
//  CTAs [0,64):    LSTM; W_hh loaded fp32 -> split hi/lo in registers ->
//                  smem (no pre-split kernel). Gates via 2-pass mma.
//  CTAs [64,143):  FC worker j owns out cols [j*128,+128); fc_W tile loaded
//                  fp32 -> fp16 in registers -> smem (no pre-split kernel).
// Dataflow sync: thread's uint4 slice (srcq = tid & 63) has exactly one
// producer CTA; wait on flag[srcq] only, with nanosleep backoff.
#define LTS 520
#define L_WROW (32 * LTS * 2)               // 33280
#define OFF_WH 0
#define OFF_WL (OFF_WH + L_WROW)
#define OFF_AH (OFF_WL + L_WROW)
#define OFF_GT (OFF_AH + L_WROW)
#define LSMEM  (OFF_GT + 32 * 33 * 4)       // 104064
// FC layout
#define FTS 520
#define OFF_FB   0
#define FB_BYTES (128 * FTS * 2)            // 133120
#define OFF_FAH  (OFF_FB + FB_BYTES)
#define OFF_FBS  (OFF_FAH + 32 * FTS * 2)   // 166400
#define FSMEM    (OFF_FBS + 512)            // 166912
#define FUSED_SMEM (FSMEM > LSMEM ? FSMEM : LSMEM)

__global__ void __launch_bounds__(256, 1)
fused_lstm_fc(const float* __restrict__ Whh, const float* __restrict__ fcW,
              const float* __restrict__ fc_b, float* __restrict__ out)
{
    extern __shared__ uint8_t dyn[];
    const int tid  = threadIdx.x;
    const int bx   = blockIdx.x;
    const int w    = tid >> 5;
    const int lane = tid & 31;
    const uint32_t sb = smem_u32(dyn);
    const int srcq = tid & 63;

    if (bx < LNCTA) {
        // =================== LSTM role ===================
        float* gates = (float*)(dyn + OFF_GT);
        const uint32_t aWH = sb + OFF_WH;
        const uint32_t aWL = sb + OFF_WL;
        const uint32_t aAH = sb + OFF_AH;

        // load W_hh slice fp32 -> split hi/lo -> smem (one-time)
        {
            const float4* ws = (const float4*)Whh;
#pragma unroll
            for (int it = 0; it < 16; ++it) {
                int idx = tid + it * 256;          // 0..4095
                int r = idx >> 7, qf = idx & 127;  // row 0..31, float4 0..127
                int gr = (r >> 3) * 512 + bx * 8 + (r & 7);
                float4 v = ws[(size_t)gr * 128 + qf];
                uint2 hi, lo;
                split4(v, hi, lo);
                *(uint2*)(dyn + OFF_WH + (r * LTS + qf * 4) * 2) = hi;
                *(uint2*)(dyn + OFF_WL + (r * LTS + qf * 4) * 2) = lo;
            }
        }

        const int mt = w & 1;
        const int nt = w >> 1;
        const int rowA  = mt * 16 + (lane & 15);
        const int colA8 = (lane >> 4) << 3;
        const int rowB  = nt * 8 + (lane & 7);
        const int colB8 = (lane >> 3) << 3;
        const int gq = lane >> 2, tq = lane & 3;

        float c_state = 0.f;
        const int jh = bx * 8 + w;
        __syncthreads();

        for (int t = 0; t < 64; ++t) {
            float gpre[4];
#pragma unroll
            for (int g = 0; g < 4; ++g)
                gpre[g] = __ldcg(&g_Gin[(size_t)t * (G_ * B_)
                                        + (size_t)(g * 512 + jh) * B_ + lane]);

            if (t > 0) {
                // ---- dataflow staging: wait on my producer, stage its slice ----
                wait_flag(srcq, (unsigned)t);
                const uint4* hh = (const uint4*)(g_hsb + (size_t)(t - 1) * B_ * H_);
#pragma unroll
                for (int it = 0; it < 8; ++it) {
                    int idx = tid + it * 256;          // = b*64 + srcq
                    int b = idx >> 6;
                    cpa16(aAH + (b * LTS + srcq * 8) * 2, hh + idx);
                }
                CP_COMMIT();
                CP_WAIT(0);
                __syncthreads();

                // ---- gates = h @ [W_hi; W_lo]^T : 2 chains x 32 k-steps ----
                float d0[4] = {0,0,0,0}, d1[4] = {0,0,0,0};
#pragma unroll
                for (int kb = 0; kb < 16; ++kb) {
                    uint32_t aH0[4], aH1[4], bH[4], bL[4];
                    ldsm4(aH0[0],aH0[1],aH0[2],aH0[3], aAH + (rowA*LTS + kb*32      + colA8)*2);
                    ldsm4(aH1[0],aH1[1],aH1[2],aH1[3], aAH + (rowA*LTS + kb*32 + 16 + colA8)*2);
                    ldsm4(bH[0],bH[1],bH[2],bH[3],     aWH + (rowB*LTS + kb*32 + colB8)*2);
                    ldsm4(bL[0],bL[1],bL[2],bL[3],     aWL + (rowB*LTS + kb*32 + colB8)*2);
                    mma_f16(d0, aH0, bH + 0);  mma_f16(d0, aH1, bH + 2);
                    mma_f16(d1, aH0, bL + 0);  mma_f16(d1, aH1, bL + 2);
                }
                {
                    int r0 = mt * 16 + gq;
                    int cc = nt * 8 + tq * 2;
                    gates[r0 * 33 + cc]           = d0[0] + d1[0];
                    gates[r0 * 33 + cc + 1]       = d0[1] + d1[1];
                    gates[(r0 + 8) * 33 + cc]     = d0[2] + d1[2];
                    gates[(r0 + 8) * 33 + cc + 1] = d0[3] + d1[3];
                }
            }
            __syncthreads();

            {
                const int b = lane;
                float gv[4];
#pragma unroll
                for (int g = 0; g < 4; ++g) {
                    float s = gpre[g];
                    if (t > 0) s += gates[b * 33 + g * 8 + w];
                    gv[g] = s;
                }
                float i_ = sigmoidf_(gv[0]);
                float f_ = sigmoidf_(gv[1]);
                float gg = tanhf(gv[2]);
                float o_ = sigmoidf_(gv[3]);
                c_state = f_ * c_state + i_ * gg;
                float h = o_ * tanhf(c_state);
                g_hsb[(size_t)t * B_ * H_ + b * 512 + jh] = __float2half(h);
            }

            __syncthreads();
            if (tid == 0) st_rel(&g_flags[bx * 32], (unsigned)(t + 1));
        }
    } else {
        // =================== FC worker role ===================
        const int j = bx - LNCTA;            // 0..78
        const int n0 = j * 128;
        float* bias_s = (float*)(dyn + OFF_FBS);
        const uint32_t aFB = sb + OFF_FB;
        const uint32_t aAH = sb + OFF_FAH;

        // load fc_W tile fp32 -> fp16 -> smem (one-time, hidden behind step 0)
        {
            const float4* fw = (const float4*)fcW;
#pragma unroll
            for (int it = 0; it < 64; ++it) {
                int idx = tid + it * 256;          // 0..16383
                int r = idx >> 7, qf = idx & 127;  // row 0..127, float4 0..127
                int n = n0 + r;
                float4 v = (n < V_) ? fw[(size_t)n * 128 + qf]
                                    : make_float4(0.f, 0.f, 0.f, 0.f);
                __half2 h0 = __floats2half2_rn(v.x, v.y);
                __half2 h1 = __floats2half2_rn(v.z, v.w);
                *(uint2*)(dyn + OFF_FB + (r * FTS + qf * 4) * 2)
                    = make_uint2(h2u(h0), h2u(h1));
            }
        }
        for (int i = tid; i < 128; i += 256) {
            int n = n0 + i;
            bias_s[i] = (n < V_) ? fc_b[n] : 0.f;
        }
        __syncthreads();

        const int rowA  = lane & 15;
        const int colA8 = (lane >> 4) << 3;
        const int g2    = lane >> 3;
        const int rowB  = w * 16 + ((g2 & 2) << 2) + (lane & 7);
        const int colB8 = (g2 & 1) << 3;
        const int gq = lane >> 2, tq = lane & 3;

        for (int t = 0; t < 64; ++t) {
            wait_flag(srcq, (unsigned)(t + 1));
            {
                const uint4* hh = (const uint4*)(g_hsb + (size_t)t * B_ * H_);
#pragma unroll
                for (int it = 0; it < 8; ++it) {
                    int idx = tid + it * 256;          // = b*64 + srcq
                    int b = idx >> 6;
                    cpa16(aAH + (b * FTS + srcq * 8) * 2, hh + idx);
                }
                CP_COMMIT();
                CP_WAIT(0);
                __syncthreads();
            }

            // 1-pass mma: out32x16 = h @ Btile^T
            float d[2][2][4];
#pragma unroll
            for (int i = 0; i < 2; i++)
#pragma unroll
                for (int jn = 0; jn < 2; jn++)
#pragma unroll
                    for (int q = 0; q < 4; q++) d[i][jn][q] = 0.f;
#pragma unroll
            for (int kb = 0; kb < 32; ++kb) {
                uint32_t aH[2][4], b[2][2];
                ldsm4(aH[0][0],aH[0][1],aH[0][2],aH[0][3], aAH + ((rowA     )*FTS + kb*16 + colA8)*2);
                ldsm4(aH[1][0],aH[1][1],aH[1][2],aH[1][3], aAH + ((rowA + 16)*FTS + kb*16 + colA8)*2);
                ldsm4(b[0][0], b[0][1], b[1][0], b[1][1],  aFB + (rowB*FTS + kb*16 + colB8)*2);
#pragma unroll
                for (int mb = 0; mb < 2; ++mb)
#pragma unroll
                    for (int nb = 0; nb < 2; ++nb)
                        mma_f16(d[mb][nb], aH[mb], b[nb]);
            }

#pragma unroll
            for (int mb = 0; mb < 2; ++mb) {
#pragma unroll
                for (int half = 0; half < 2; ++half) {
                    int b = mb * 16 + gq + half * 8;
                    float* crow = out + (size_t)b * (T_ * V_) + (size_t)t * V_;
#pragma unroll
                    for (int nb = 0; nb < 2; ++nb) {
                        int nl = w * 16 + nb * 8 + tq * 2;
                        int n  = n0 + nl;
                        if (n < V_) {
                            float2 o;
                            o.x = d[mb][nb][half * 2 + 0] + bias_s[nl];
                            o.y = d[mb][nb][half * 2 + 1] + bias_s[nl + 1];
                            *(float2*)&crow[n] = o;
                        }
                    }
                }
            }
            __syncthreads();
        }
    }
}

// ------------------------- launch ------------------------------------------
extern "C" void kernel_launch(void* const* d_in, const int* in_sizes, int n_in,
                              void* d_out, int out_size)
{
    const float* features = (const float*)d_in[0];
    const int*   captions = (const int*)d_in[1];
    // d_in[2] = forward_approach (unused)
    const float* embed = (const float*)d_in[3];
    const float* W_ih  = (const float*)d_in[4];
    const float* W_hh  = (const float*)d_in[5];
    const float* b_ih  = (const float*)d_in[6];
    const float* b_hh  = (const float*)d_in[7];
    const float* fc_W  = (const float*)d_in[8];
    const float* fc_b  = (const float*)d_in[9];
    float* out = (float*)d_out;

    float *pGin, *pbias;
    __half *pXh, *pXl, *pWih_h;
    cudaGetSymbolAddress((void**)&pGin,   g_Gin);
    cudaGetSymbolAddress((void**)&pbias,  g_biasg);
    cudaGetSymbolAddress((void**)&pXh,    g_Xh);
    cudaGetSymbolAddress((void**)&pXl,    g_Xl);
    cudaGetSymbolAddress((void**)&pWih_h, g_Wih_h);

    const int SMEM_G2 = 2 * 3 * TILE_B + 512;    // 61952
    cudaFuncSetAttribute(gin_gemm, cudaFuncAttributeMaxDynamicSharedMemorySize, SMEM_G2);
    cudaFuncSetAttribute(fused_lstm_fc, cudaFuncAttributeMaxDynamicSharedMemorySize, FUSED_SMEM);

    // 1) build split X + fused bias + reset barrier flags
    prep_kernel<<<(T_ * B_ * E_ / 4) / 256, 256>>>(
        (const float4*)features, captions, (const float4*)embed,
        (const float4*)b_ih, (const float4*)b_hh);

    // 2) W_ih hi-only split (W_hh and fc_W are converted inside the fused kernel)
    split_hi_kernel<<<(G_ * E_ / 4 + 255) / 256, 256>>>(
        (const float4*)W_ih, (uint2*)pWih_h, G_ * E_ / 4);

    // 3) Gin[t][n][b] = X @ W_ih^T + (b_ih + b_hh)   (fp16 2-pass)
    gin_gemm<<<dim3(G_ / 128, (T_ * B_) / 128), 256, SMEM_G2>>>(
        pXh, pXl, pWih_h, pbias, pGin);

    // 4) fused persistent LSTM + FC (in-kernel weight conversion)
    fused_lstm_fc<<<LNCTA + FNCTA, 256, FUSED_SMEM>>>(W_hh, fc_W, fc_b, out);
}